// round 7
// baseline (speedup 1.0000x reference)
#include <cuda_runtime.h>

#define B_TOT 4096
#define T_ENC 168
#define T_DEC 24
#define NF    32
#define NT    8
#define HID   64
#define NG    256   // 4*HID

// Phase-1 scratch: XG0[b][t][g] = x[b,t,:] @ Wih0^T + bih0 + bhh0  (704 MB)
__device__ float g_xg0[(size_t)B_TOT * T_ENC * NG];

typedef unsigned long long u64;

// ---------------------------------------------------------------------------
// packed fp32 + fast activation helpers
// ---------------------------------------------------------------------------
__device__ __forceinline__ u64 pack2(float v) {
    u64 r;
    unsigned int b = __float_as_uint(v);
    asm("mov.b64 %0, {%1, %2};" : "=l"(r) : "r"(b), "r"(b));
    return r;
}
__device__ __forceinline__ void fma2(u64& acc, u64 a, u64 b) {
    asm("fma.rn.f32x2 %0, %1, %2, %0;" : "+l"(acc) : "l"(a), "l"(b));
}
__device__ __forceinline__ void add2(u64& acc, u64 a) {
    asm("add.rn.f32x2 %0, %0, %1;" : "+l"(acc) : "l"(a));
}
__device__ __forceinline__ float2 unpack2(u64 v) {
    unsigned int lo, hi;
    asm("mov.b64 {%0, %1}, %2;" : "=r"(lo), "=r"(hi) : "l"(v));
    return make_float2(__uint_as_float(lo), __uint_as_float(hi));
}
__device__ __forceinline__ float ftanh(float x) {      // MUFU.TANH
    float y;
    asm("tanh.approx.f32 %0, %1;" : "=f"(y) : "f"(x));
    return y;
}
__device__ __forceinline__ float fsig(float x) {       // 1 MUFU + 1 FMA
    return fmaf(ftanh(0.5f * x), 0.5f, 0.5f);
}

// interleaved-weight scatter index for source gate g, row k (float index)
// layout: u64[k][j2(0..31)][blk(0..3)]
__device__ __forceinline__ int widx(int k, int g) {
    int e = g & 1, j2 = (g >> 1) & 31, b = g >> 6;
    return ((k * 32 + j2) * 4 + b) * 2 + e;
}

// ---------------------------------------------------------------------------
// Phase-1 GEMM (xg0, 256 thr): 4 rows x 8 cols per thread, k-major weights
// ---------------------------------------------------------------------------
__device__ __forceinline__ void gemm2(
    u64 acc[4][4], const float* __restrict__ hT, int hstride,
    const float* __restrict__ ws, int wstride, int K, int r0, int jcol)
{
#pragma unroll 2
    for (int k = 0; k < K; k += 4) {
#pragma unroll
        for (int kk = 0; kk < 4; kk++) {
            float4 a = *(const float4*)&hT[(k + kk) * hstride + r0];
            const float* wr = ws + (k + kk) * wstride + jcol;
            u64 w0 = *(const u64*)(wr);
            u64 w1 = *(const u64*)(wr + 64);
            u64 w2 = *(const u64*)(wr + 128);
            u64 w3 = *(const u64*)(wr + 192);
            u64 h0 = pack2(a.x), h1 = pack2(a.y), h2 = pack2(a.z), h3 = pack2(a.w);
            fma2(acc[0][0], h0, w0); fma2(acc[0][1], h0, w1);
            fma2(acc[0][2], h0, w2); fma2(acc[0][3], h0, w3);
            fma2(acc[1][0], h1, w0); fma2(acc[1][1], h1, w1);
            fma2(acc[1][2], h1, w2); fma2(acc[1][3], h1, w3);
            fma2(acc[2][0], h2, w0); fma2(acc[2][1], h2, w1);
            fma2(acc[2][2], h2, w2); fma2(acc[2][3], h2, w3);
            fma2(acc[3][0], h3, w0); fma2(acc[3][1], h3, w1);
            fma2(acc[3][2], h3, w2); fma2(acc[3][3], h3, w3);
        }
    }
}

// ---------------------------------------------------------------------------
// Phase-2 GEMM (512 thr): 2 rows x 8 cols per thread, interleaved weights.
//   per k: 1 LDS.64 (hT) + 2 LDS.128 (w, 4-addr broadcast) + 2 pack + 8 FMA2
// ---------------------------------------------------------------------------
__device__ __forceinline__ void gemm2i(
    u64 acc[2][4], const float* __restrict__ hT,
    const u64* __restrict__ wI, int K, int r0, int j2)
{
#pragma unroll 4
    for (int k = 0; k < K; k++) {
        float2 a = *(const float2*)&hT[k * 32 + r0];
        const u64* wr = wI + (k * 32 + j2) * 4;
        ulonglong2 wA = *(const ulonglong2*)(wr);       // blk0, blk1
        ulonglong2 wB = *(const ulonglong2*)(wr + 2);   // blk2, blk3
        u64 h0 = pack2(a.x), h1 = pack2(a.y);
        fma2(acc[0][0], h0, wA.x); fma2(acc[0][1], h0, wA.y);
        fma2(acc[0][2], h0, wB.x); fma2(acc[0][3], h0, wB.y);
        fma2(acc[1][0], h1, wA.x); fma2(acc[1][1], h1, wA.y);
        fma2(acc[1][2], h1, wB.x); fma2(acc[1][3], h1, wB.y);
    }
}

// PyTorch gate order: blk0=i, blk1=f, blk2=g, blk3=o
__device__ __forceinline__ void cell_update2(
    const u64 acc[2][4], float c[2][2], float hn[2][2])
{
#pragma unroll
    for (int rr = 0; rr < 2; rr++) {
        float2 gi = unpack2(acc[rr][0]);
        float2 gf = unpack2(acc[rr][1]);
        float2 gg = unpack2(acc[rr][2]);
        float2 go = unpack2(acc[rr][3]);
        float cn0 = fmaf(fsig(gf.x), c[rr][0], fsig(gi.x) * ftanh(gg.x));
        float cn1 = fmaf(fsig(gf.y), c[rr][1], fsig(gi.y) * ftanh(gg.y));
        c[rr][0] = cn0; c[rr][1] = cn1;
        hn[rr][0] = fsig(go.x) * ftanh(cn0);
        hn[rr][1] = fsig(go.y) * ftanh(cn1);
    }
}

// store hn (2 rows x 2 j) into transposed hT[j][row] (stride 32)
__device__ __forceinline__ void h_store2(
    const float hn[2][2], float* __restrict__ hT, int r0, int jcol)
{
    *(float2*)&hT[(jcol + 0) * 32 + r0] = make_float2(hn[0][0], hn[1][0]);
    *(float2*)&hT[(jcol + 1) * 32 + r0] = make_float2(hn[0][1], hn[1][1]);
}

// ---------------------------------------------------------------------------
// Phase 1: persistent XG0 kernel (R6-proven). grid=128, 256 threads.
// ---------------------------------------------------------------------------
#define XS_STRIDE 36
__global__ void __launch_bounds__(256) xg0_kernel(
    const float* __restrict__ x, const float* __restrict__ Wih0,
    const float* __restrict__ bih0, const float* __restrict__ bhh0)
{
    __shared__ float xs[NF * XS_STRIDE];   // transposed [k][row]
    __shared__ float ws[NF * 258];         // k-major padded
    __shared__ float bs[NG];

    const int tid = threadIdx.x;
    const int b0 = blockIdx.x * 32;

    for (int idx = tid; idx < NG * NF; idx += 256) {    // coalesced LDG
        int k = idx & 31, g = idx >> 5;                  // Wih0[g][k]
        ws[k * 258 + g] = Wih0[idx];
    }
    if (tid < NG) bs[tid] = bih0[tid] + bhh0[tid];

    const int wid = tid >> 5, lane = tid & 31;
    const int r0 = (lane >> 2) * 4;
    const int jcol = wid * 8 + (lane & 3) * 2;

    const int xr = tid >> 3;             // 0..31
    const int k4 = (tid & 7) * 4;        // 0,4,..,28

    float4 xv = *(const float4*)(x + ((size_t)(b0 + xr) * T_ENC + 0) * NF + k4);
    __syncthreads();                     // ws/bs ready

    for (int t = 0; t < T_ENC; t++) {
        xs[(k4 + 0) * XS_STRIDE + xr] = xv.x;
        xs[(k4 + 1) * XS_STRIDE + xr] = xv.y;
        xs[(k4 + 2) * XS_STRIDE + xr] = xv.z;
        xs[(k4 + 3) * XS_STRIDE + xr] = xv.w;
        __syncthreads();                 // xs ready

        if (t + 1 < T_ENC)               // prefetch next tile during GEMM
            xv = *(const float4*)(x + ((size_t)(b0 + xr) * T_ENC + t + 1) * NF + k4);

        u64 acc[4][4];
#pragma unroll
        for (int blk = 0; blk < 4; blk++) {
            u64 b = *(const u64*)&bs[blk * 64 + jcol];
#pragma unroll
            for (int rr = 0; rr < 4; rr++) acc[rr][blk] = b;
        }
        gemm2(acc, xs, XS_STRIDE, ws, 258, NF, r0, jcol);

#pragma unroll
        for (int rr = 0; rr < 4; rr++) {
            float* dst = g_xg0 + ((size_t)(b0 + r0 + rr) * T_ENC + t) * NG + jcol;
#pragma unroll
            for (int blk = 0; blk < 4; blk++)
                *(u64*)(dst + blk * 64) = acc[rr][blk];
        }
        __syncthreads();                 // WAR: gemm done reading xs
    }
}

// ---------------------------------------------------------------------------
// Phase 2 smem layout (floats). h0A|h1A contiguous (decoder L1 K=128).
// h1B overlays decoder-only b0s/fcw/fcb/dinT; h0B overlays w0 rows 64..71.
// ---------------------------------------------------------------------------
#define SM_W0    0                          // 72 rows * 256 = 18432
#define SM_H0B   (SM_W0 + 64 * NG)          // enc h0 buffer B (w0 rows 64..71)
#define SM_W1    (SM_W0 + 72 * NG)          // 128 rows * 256 -> 51200
#define SM_B1    (SM_W1 + 128 * NG)         // 51200..51456
#define SM_H0    (SM_B1 + NG)               // 51456..53504  h0A
#define SM_H1    (SM_H0 + HID * 32)         // 53504..55552  h1A
#define SM_H1B   (SM_H1 + HID * 32)         // 55552..57600  h1B (encoder)
#define SM_B0    SM_H1B                     // 55552..55808  (decoder overlay)
#define SM_FCW   (SM_B0 + NG)               // 55808..56320
#define SM_FCB   (SM_FCW + HID * NT)        // 56320..56336
#define SM_DIN   (SM_FCB + 16)              // 56336..56592
#define SM_TOTAL (SM_H1B + HID * 32)        // 57600 fl = 230400 B
#define SMEM_BYTES (SM_TOTAL * 4)

#define NTHR 512

__global__ void __launch_bounds__(NTHR, 1) seq2seq_kernel(
    const float* __restrict__ eWhh0,
    const float* __restrict__ eWih1, const float* __restrict__ eWhh1,
    const float* __restrict__ ebih1, const float* __restrict__ ebhh1,
    const float* __restrict__ dWih0, const float* __restrict__ dWhh0,
    const float* __restrict__ dbih0, const float* __restrict__ dbhh0,
    const float* __restrict__ dWih1, const float* __restrict__ dWhh1,
    const float* __restrict__ dbih1, const float* __restrict__ dbhh1,
    const float* __restrict__ fcW, const float* __restrict__ fcBias,
    float* __restrict__ out)
{
    extern __shared__ float sm[];
    float* w0f = sm + SM_W0;
    float* w1f = sm + SM_W1;
    const u64* w0I = (const u64*)w0f;
    const u64* w1I = (const u64*)w1f;
    float* b0s = sm + SM_B0;
    float* b1s = sm + SM_B1;
    float* fcw = sm + SM_FCW;
    float* fcb = sm + SM_FCB;
    float* dinT = sm + SM_DIN;
    float* h0A = sm + SM_H0;
    float* h0B = sm + SM_H0B;
    float* h1A = sm + SM_H1;
    float* h1B = sm + SM_H1B;

    const int tid = threadIdx.x;
    const int b0 = blockIdx.x * 32;
    const int wid = tid >> 5, lane = tid & 31;
    // 512-thread tile: 2 rows x (2 cols x 4 gate-blocks) per thread
    const int rh = wid >> 3, w8 = wid & 7;
    const int r0 = rh * 16 + (lane >> 2) * 2;     // rows {0,2,...,30} (+0/+16)
    const int j2 = w8 * 4 + (lane & 3);           // 0..31
    const int jcol = j2 * 2;

    // ---- load encoder weights, interleaved (w0 rows 0..63 only) ----
    for (int idx = tid; idx < HID * NG; idx += NTHR) {
        int k = idx >> 8, g = idx & 255;
        w0f[widx(k, g)] = eWhh0[g * HID + k];
        w1f[widx(k, g)] = eWih1[g * HID + k];
        w1f[widx(k + HID, g)] = eWhh1[g * HID + k];
    }
    if (tid < NG) b1s[tid] = ebih1[tid] + ebhh1[tid];
    for (int idx = tid; idx < HID * 32; idx += NTHR) { h0A[idx] = 0.f; h1A[idx] = 0.f; }
    __syncthreads();

    float c0[2][2] = {{0,0},{0,0}};
    float c1[2][2] = {{0,0},{0,0}};
    u64 acc[2][4];
    u64 xg[2][4];
    float hn[2][2];

    // ================= encoder: one barrier per step =================
    for (int t = 0; t < T_ENC; t++) {
        float* h0rd = (t & 1) ? h0B : h0A;
        float* h0wr = (t & 1) ? h0A : h0B;
        float* h1rd = (t & 1) ? h1B : h1A;
        float* h1wr = (t & 1) ? h1A : h1B;

        // layer 0: prefetch XG0, GEMM from zero, add at end
#pragma unroll
        for (int rr = 0; rr < 2; rr++) {
            const float* src =
                g_xg0 + ((size_t)(b0 + r0 + rr) * T_ENC + t) * NG + jcol;
#pragma unroll
            for (int blk = 0; blk < 4; blk++)
                xg[rr][blk] = *(const u64*)(src + blk * 64);
        }
#pragma unroll
        for (int rr = 0; rr < 2; rr++)
#pragma unroll
            for (int blk = 0; blk < 4; blk++) acc[rr][blk] = 0ull;

        gemm2i(acc, h0rd, w0I, HID, r0, j2);
#pragma unroll
        for (int rr = 0; rr < 2; rr++)
#pragma unroll
            for (int blk = 0; blk < 4; blk++) add2(acc[rr][blk], xg[rr][blk]);
        cell_update2(acc, c0, hn);
        h_store2(hn, h0wr, r0, jcol);      // WAR-safe: alternate buffer

        __syncthreads();                    // publishes h0(t), h1(t-1)

        // layer 1: Wih1(h0 new) + Whh1(h1 old), both K=64
#pragma unroll
        for (int blk = 0; blk < 4; blk++) {
            u64 b = *(const u64*)&b1s[blk * 64 + jcol];
#pragma unroll
            for (int rr = 0; rr < 2; rr++) acc[rr][blk] = b;
        }
        gemm2i(acc, h0wr, w1I, HID, r0, j2);
        gemm2i(acc, h1rd, w1I + HID * 32 * 4, HID, r0, j2);
        cell_update2(acc, c1, hn);
        h_store2(hn, h1wr, r0, jcol);      // WAR-safe: alternate buffer
    }
    __syncthreads();                        // buffers/weights about to be reused

    // ---- swap in decoder weights ----
    for (int idx = tid; idx < NT * NG; idx += NTHR) {    // dec_Wih0 -> rows 0..7
        int k = idx >> 8, g = idx & 255;
        w0f[widx(k, g)] = dWih0[g * NT + k];
    }
    for (int idx = tid; idx < HID * NG; idx += NTHR) {
        int k = idx >> 8, g = idx & 255;
        w0f[widx(k + NT, g)] = dWhh0[g * HID + k];        // rows 8..71
        w1f[widx(k, g)] = dWih1[g * HID + k];
        w1f[widx(k + HID, g)] = dWhh1[g * HID + k];
    }
    if (tid < NG) {
        b0s[tid] = dbih0[tid] + dbhh0[tid];
        b1s[tid] = dbih1[tid] + dbhh1[tid];
    }
    for (int idx = tid; idx < HID * NT; idx += NTHR) {    // fc_W[o][j] -> fcw[j][o]
        int j = idx >> 3, o = idx & 7;
        fcw[idx] = fcW[o * HID + j];
    }
    if (tid < NT) fcb[tid] = fcBias[tid];
    for (int idx = tid; idx < NT * 32; idx += NTHR) dinT[idx] = 0.f;
    __syncthreads();

    // ================= decoder =================
    for (int s = 0; s < T_DEC; s++) {
        // layer 0: din (K=8) + h0 (K=64)
#pragma unroll
        for (int blk = 0; blk < 4; blk++) {
            u64 b = *(const u64*)&b0s[blk * 64 + jcol];
#pragma unroll
            for (int rr = 0; rr < 2; rr++) acc[rr][blk] = b;
        }
        gemm2i(acc, dinT, w0I, NT, r0, j2);
        gemm2i(acc, h0A, w0I + NT * 32 * 4, HID, r0, j2);
        cell_update2(acc, c0, hn);
        __syncthreads();
        h_store2(hn, h0A, r0, jcol);
        __syncthreads();

        // layer 1: [h0A|h1A] contiguous, K=128
#pragma unroll
        for (int blk = 0; blk < 4; blk++) {
            u64 b = *(const u64*)&b1s[blk * 64 + jcol];
#pragma unroll
            for (int rr = 0; rr < 2; rr++) acc[rr][blk] = b;
        }
        gemm2i(acc, h0A, w1I, 2 * HID, r0, j2);
        cell_update2(acc, c1, hn);
        __syncthreads();
        h_store2(hn, h1A, r0, jcol);
        __syncthreads();                 // h1 visible to FC

        // FC: threads 0..255, one (row, out) each; h1A transposed [j][row]
        if (tid < 256) {
            int r = tid >> 3, o = tid & 7;
            float a = fcb[o];
#pragma unroll 8
            for (int j = 0; j < HID; j++)
                a = fmaf(h1A[j * 32 + r], fcw[j * NT + o], a);
            out[((size_t)(b0 + r) * T_DEC + s) * NT + o] = a;
            dinT[o * 32 + r] = a;
        }
        __syncthreads();                 // dinT visible to next layer 0
    }
}

// ---------------------------------------------------------------------------
extern "C" void kernel_launch(void* const* d_in, const int* in_sizes, int n_in,
                              void* d_out, int out_size)
{
    const float* x     = (const float*)d_in[0];
    const float* eWih0 = (const float*)d_in[1];
    const float* eWhh0 = (const float*)d_in[2];
    const float* ebih0 = (const float*)d_in[3];
    const float* ebhh0 = (const float*)d_in[4];
    const float* eWih1 = (const float*)d_in[5];
    const float* eWhh1 = (const float*)d_in[6];
    const float* ebih1 = (const float*)d_in[7];
    const float* ebhh1 = (const float*)d_in[8];
    const float* dWih0 = (const float*)d_in[9];
    const float* dWhh0 = (const float*)d_in[10];
    const float* dbih0 = (const float*)d_in[11];
    const float* dbhh0 = (const float*)d_in[12];
    const float* dWih1 = (const float*)d_in[13];
    const float* dWhh1 = (const float*)d_in[14];
    const float* dbih1 = (const float*)d_in[15];
    const float* dbhh1 = (const float*)d_in[16];
    const float* fcW   = (const float*)d_in[17];
    const float* fcb   = (const float*)d_in[18];
    float* out = (float*)d_out;

    cudaFuncSetAttribute(seq2seq_kernel,
                         cudaFuncAttributeMaxDynamicSharedMemorySize, SMEM_BYTES);

    xg0_kernel<<<B_TOT / 32, 256>>>(x, eWih0, ebih0, ebhh0);
    seq2seq_kernel<<<B_TOT / 32, NTHR, SMEM_BYTES>>>(
        eWhh0, eWih1, eWhh1, ebih1, ebhh1,
        dWih0, dWhh0, dbih0, dbhh0, dWih1, dWhh1, dbih1, dbhh1,
        fcW, fcb, out);
}

// round 8
// speedup vs baseline: 1.3584x; 1.3584x over previous
#include <cuda_runtime.h>

#define B_TOT 4096
#define T_ENC 168
#define T_DEC 24
#define NF    32
#define NT    8
#define HID   64
#define NG    256   // 4*HID

// Phase-1 scratch: XG0[b][t][g] = x[b,t,:] @ Wih0^T + bih0 + bhh0  (704 MB)
__device__ float g_xg0[(size_t)B_TOT * T_ENC * NG];

typedef unsigned long long u64;

// ---------------------------------------------------------------------------
// packed fp32 + fast activation helpers
// ---------------------------------------------------------------------------
__device__ __forceinline__ u64 pack2(float v) {
    u64 r;
    unsigned int b = __float_as_uint(v);
    asm("mov.b64 %0, {%1, %2};" : "=l"(r) : "r"(b), "r"(b));
    return r;
}
__device__ __forceinline__ void fma2(u64& acc, u64 a, u64 b) {
    asm("fma.rn.f32x2 %0, %1, %2, %0;" : "+l"(acc) : "l"(a), "l"(b));
}
__device__ __forceinline__ void add2(u64& acc, u64 a) {
    asm("add.rn.f32x2 %0, %0, %1;" : "+l"(acc) : "l"(a));
}
__device__ __forceinline__ float2 unpack2(u64 v) {
    unsigned int lo, hi;
    asm("mov.b64 {%0, %1}, %2;" : "=r"(lo), "=r"(hi) : "l"(v));
    return make_float2(__uint_as_float(lo), __uint_as_float(hi));
}
__device__ __forceinline__ float ftanh(float x) {      // MUFU.TANH
    float y;
    asm("tanh.approx.f32 %0, %1;" : "=f"(y) : "f"(x));
    return y;
}
__device__ __forceinline__ float fsig(float x) {       // 1 MUFU + 1 FMA
    return fmaf(ftanh(0.5f * x), 0.5f, 0.5f);
}

// interleaved-weight scatter index for source gate g, row k (float index)
// layout: u64[k][j2(0..31)][blk(0..3)]
__device__ __forceinline__ int widx(int k, int g) {
    int e = g & 1, j2 = (g >> 1) & 31, b = g >> 6;
    return ((k * 32 + j2) * 4 + b) * 2 + e;
}

// ---------------------------------------------------------------------------
// Phase-1 GEMM (xg0): 4 rows x 8 cols per thread, k-major weights
// ---------------------------------------------------------------------------
__device__ __forceinline__ void gemm2(
    u64 acc[4][4], const float* __restrict__ hT, int hstride,
    const float* __restrict__ ws, int wstride, int K, int r0, int jcol)
{
#pragma unroll 2
    for (int k = 0; k < K; k += 4) {
#pragma unroll
        for (int kk = 0; kk < 4; kk++) {
            float4 a = *(const float4*)&hT[(k + kk) * hstride + r0];
            const float* wr = ws + (k + kk) * wstride + jcol;
            u64 w0 = *(const u64*)(wr);
            u64 w1 = *(const u64*)(wr + 64);
            u64 w2 = *(const u64*)(wr + 128);
            u64 w3 = *(const u64*)(wr + 192);
            u64 h0 = pack2(a.x), h1 = pack2(a.y), h2 = pack2(a.z), h3 = pack2(a.w);
            fma2(acc[0][0], h0, w0); fma2(acc[0][1], h0, w1);
            fma2(acc[0][2], h0, w2); fma2(acc[0][3], h0, w3);
            fma2(acc[1][0], h1, w0); fma2(acc[1][1], h1, w1);
            fma2(acc[1][2], h1, w2); fma2(acc[1][3], h1, w3);
            fma2(acc[2][0], h2, w0); fma2(acc[2][1], h2, w1);
            fma2(acc[2][2], h2, w2); fma2(acc[2][3], h2, w3);
            fma2(acc[3][0], h3, w0); fma2(acc[3][1], h3, w1);
            fma2(acc[3][2], h3, w2); fma2(acc[3][3], h3, w3);
        }
    }
}

// ---------------------------------------------------------------------------
// Phase-2 GEMM (R3/R5-proven): 4 rows x 8 cols, interleaved weights.
// ---------------------------------------------------------------------------
__device__ __forceinline__ void gemm2i(
    u64 acc[4][4], const float* __restrict__ hT,
    const u64* __restrict__ wI, int K, int r0, int j2)
{
#pragma unroll 4
    for (int k = 0; k < K; k++) {
        float4 a = *(const float4*)&hT[k * 32 + r0];
        const u64* wr = wI + (k * 32 + j2) * 4;
        ulonglong2 wA = *(const ulonglong2*)(wr);       // blk0, blk1
        ulonglong2 wB = *(const ulonglong2*)(wr + 2);   // blk2, blk3
        u64 h0 = pack2(a.x), h1 = pack2(a.y), h2 = pack2(a.z), h3 = pack2(a.w);
        fma2(acc[0][0], h0, wA.x); fma2(acc[0][1], h0, wA.y);
        fma2(acc[0][2], h0, wB.x); fma2(acc[0][3], h0, wB.y);
        fma2(acc[1][0], h1, wA.x); fma2(acc[1][1], h1, wA.y);
        fma2(acc[1][2], h1, wB.x); fma2(acc[1][3], h1, wB.y);
        fma2(acc[2][0], h2, wA.x); fma2(acc[2][1], h2, wA.y);
        fma2(acc[2][2], h2, wB.x); fma2(acc[2][3], h2, wB.y);
        fma2(acc[3][0], h3, wA.x); fma2(acc[3][1], h3, wA.y);
        fma2(acc[3][2], h3, wB.x); fma2(acc[3][3], h3, wB.y);
    }
}

// ---------------------------------------------------------------------------
// Fused dual GEMM: one h0 load feeds BOTH acc1 (w1 = Wih1) and acc0 (w0 = Whh0)
// 32 FMA2 per k-iter, 5 LDS, double the independent chains.
// ---------------------------------------------------------------------------
__device__ __forceinline__ void gemm2i_dual(
    u64 acc1[4][4], u64 acc0[4][4], const float* __restrict__ hT,
    const u64* __restrict__ w1, const u64* __restrict__ w0, int r0, int j2)
{
#pragma unroll 2
    for (int k = 0; k < HID; k++) {
        float4 a = *(const float4*)&hT[k * 32 + r0];
        const u64* wr1 = w1 + (k * 32 + j2) * 4;
        const u64* wr0 = w0 + (k * 32 + j2) * 4;
        ulonglong2 wA1 = *(const ulonglong2*)(wr1);
        ulonglong2 wB1 = *(const ulonglong2*)(wr1 + 2);
        ulonglong2 wA0 = *(const ulonglong2*)(wr0);
        ulonglong2 wB0 = *(const ulonglong2*)(wr0 + 2);
        u64 h0 = pack2(a.x), h1 = pack2(a.y), h2 = pack2(a.z), h3 = pack2(a.w);
        fma2(acc1[0][0], h0, wA1.x); fma2(acc1[0][1], h0, wA1.y);
        fma2(acc1[0][2], h0, wB1.x); fma2(acc1[0][3], h0, wB1.y);
        fma2(acc0[0][0], h0, wA0.x); fma2(acc0[0][1], h0, wA0.y);
        fma2(acc0[0][2], h0, wB0.x); fma2(acc0[0][3], h0, wB0.y);
        fma2(acc1[1][0], h1, wA1.x); fma2(acc1[1][1], h1, wA1.y);
        fma2(acc1[1][2], h1, wB1.x); fma2(acc1[1][3], h1, wB1.y);
        fma2(acc0[1][0], h1, wA0.x); fma2(acc0[1][1], h1, wA0.y);
        fma2(acc0[1][2], h1, wB0.x); fma2(acc0[1][3], h1, wB0.y);
        fma2(acc1[2][0], h2, wA1.x); fma2(acc1[2][1], h2, wA1.y);
        fma2(acc1[2][2], h2, wB1.x); fma2(acc1[2][3], h2, wB1.y);
        fma2(acc0[2][0], h2, wA0.x); fma2(acc0[2][1], h2, wA0.y);
        fma2(acc0[2][2], h2, wB0.x); fma2(acc0[2][3], h2, wB0.y);
        fma2(acc1[3][0], h3, wA1.x); fma2(acc1[3][1], h3, wA1.y);
        fma2(acc1[3][2], h3, wB1.x); fma2(acc1[3][3], h3, wB1.y);
        fma2(acc0[3][0], h3, wA0.x); fma2(acc0[3][1], h3, wA0.y);
        fma2(acc0[3][2], h3, wB0.x); fma2(acc0[3][3], h3, wB0.y);
    }
}

// PyTorch gate order: blk0=i, blk1=f, blk2=g, blk3=o
__device__ __forceinline__ void cell_update(
    const u64 acc[4][4], float c[4][2], float hn[4][2])
{
#pragma unroll
    for (int rr = 0; rr < 4; rr++) {
        float2 gi = unpack2(acc[rr][0]);
        float2 gf = unpack2(acc[rr][1]);
        float2 gg = unpack2(acc[rr][2]);
        float2 go = unpack2(acc[rr][3]);
        float cn0 = fmaf(fsig(gf.x), c[rr][0], fsig(gi.x) * ftanh(gg.x));
        float cn1 = fmaf(fsig(gf.y), c[rr][1], fsig(gi.y) * ftanh(gg.y));
        c[rr][0] = cn0; c[rr][1] = cn1;
        hn[rr][0] = fsig(go.x) * ftanh(cn0);
        hn[rr][1] = fsig(go.y) * ftanh(cn1);
    }
}

// store hn (4 rows x 2 j) into transposed hT[j][row] (stride 32)
__device__ __forceinline__ void h_store(
    const float hn[4][2], float* __restrict__ hT, int r0, int jcol)
{
    *(float4*)&hT[(jcol + 0) * 32 + r0] =
        make_float4(hn[0][0], hn[1][0], hn[2][0], hn[3][0]);
    *(float4*)&hT[(jcol + 1) * 32 + r0] =
        make_float4(hn[0][1], hn[1][1], hn[2][1], hn[3][1]);
}

// ---------------------------------------------------------------------------
// Phase 1: persistent XG0 kernel (R6-proven). grid=128, 256 threads.
// ---------------------------------------------------------------------------
#define XS_STRIDE 36
__global__ void __launch_bounds__(256) xg0_kernel(
    const float* __restrict__ x, const float* __restrict__ Wih0,
    const float* __restrict__ bih0, const float* __restrict__ bhh0)
{
    __shared__ float xs[NF * XS_STRIDE];   // transposed [k][row]
    __shared__ float ws[NF * 258];         // k-major padded
    __shared__ float bs[NG];

    const int tid = threadIdx.x;
    const int b0 = blockIdx.x * 32;

    for (int idx = tid; idx < NG * NF; idx += 256) {    // coalesced LDG
        int k = idx & 31, g = idx >> 5;                  // Wih0[g][k]
        ws[k * 258 + g] = Wih0[idx];
    }
    if (tid < NG) bs[tid] = bih0[tid] + bhh0[tid];

    const int wid = tid >> 5, lane = tid & 31;
    const int r0 = (lane >> 2) * 4;
    const int jcol = wid * 8 + (lane & 3) * 2;

    const int xr = tid >> 3;             // 0..31
    const int k4 = (tid & 7) * 4;        // 0,4,..,28

    float4 xv = *(const float4*)(x + ((size_t)(b0 + xr) * T_ENC + 0) * NF + k4);
    __syncthreads();                     // ws/bs ready

    for (int t = 0; t < T_ENC; t++) {
        xs[(k4 + 0) * XS_STRIDE + xr] = xv.x;
        xs[(k4 + 1) * XS_STRIDE + xr] = xv.y;
        xs[(k4 + 2) * XS_STRIDE + xr] = xv.z;
        xs[(k4 + 3) * XS_STRIDE + xr] = xv.w;
        __syncthreads();                 // xs ready

        if (t + 1 < T_ENC)               // prefetch next tile during GEMM
            xv = *(const float4*)(x + ((size_t)(b0 + xr) * T_ENC + t + 1) * NF + k4);

        u64 acc[4][4];
#pragma unroll
        for (int blk = 0; blk < 4; blk++) {
            u64 b = *(const u64*)&bs[blk * 64 + jcol];
#pragma unroll
            for (int rr = 0; rr < 4; rr++) acc[rr][blk] = b;
        }
        gemm2(acc, xs, XS_STRIDE, ws, 258, NF, r0, jcol);

#pragma unroll
        for (int rr = 0; rr < 4; rr++) {
            float* dst = g_xg0 + ((size_t)(b0 + r0 + rr) * T_ENC + t) * NG + jcol;
#pragma unroll
            for (int blk = 0; blk < 4; blk++)
                *(u64*)(dst + blk * 64) = acc[rr][blk];
        }
        __syncthreads();                 // WAR: gemm done reading xs
    }
}

// ---------------------------------------------------------------------------
// Phase 2 smem layout (floats). h0A|h1A contiguous (decoder L1 K=128).
// h1B overlays decoder-only b0s/fcw/fcb/dinT; h0B overlays w0 rows 64..71.
// ---------------------------------------------------------------------------
#define SM_W0    0                          // 72 rows * 256 = 18432
#define SM_H0B   (SM_W0 + 64 * NG)          // enc h0 buffer B (w0 rows 64..71)
#define SM_W1    (SM_W0 + 72 * NG)          // 128 rows * 256 -> 51200
#define SM_B1    (SM_W1 + 128 * NG)         // 51200..51456
#define SM_H0    (SM_B1 + NG)               // 51456..53504  h0A
#define SM_H1    (SM_H0 + HID * 32)         // 53504..55552  h1A
#define SM_H1B   (SM_H1 + HID * 32)         // 55552..57600  h1B (encoder)
#define SM_B0    SM_H1B                     // 55552..55808  (decoder overlay)
#define SM_FCW   (SM_B0 + NG)               // 55808..56320
#define SM_FCB   (SM_FCW + HID * NT)        // 56320..56336
#define SM_DIN   (SM_FCB + 16)              // 56336..56592
#define SM_TOTAL (SM_H1B + HID * 32)        // 57600 fl = 230400 B
#define SMEM_BYTES (SM_TOTAL * 4)

__global__ void __launch_bounds__(256, 1) seq2seq_kernel(
    const float* __restrict__ eWhh0,
    const float* __restrict__ eWih1, const float* __restrict__ eWhh1,
    const float* __restrict__ ebih1, const float* __restrict__ ebhh1,
    const float* __restrict__ dWih0, const float* __restrict__ dWhh0,
    const float* __restrict__ dbih0, const float* __restrict__ dbhh0,
    const float* __restrict__ dWih1, const float* __restrict__ dWhh1,
    const float* __restrict__ dbih1, const float* __restrict__ dbhh1,
    const float* __restrict__ fcW, const float* __restrict__ fcBias,
    float* __restrict__ out)
{
    extern __shared__ float sm[];
    float* w0f = sm + SM_W0;
    float* w1f = sm + SM_W1;
    const u64* w0I = (const u64*)w0f;
    const u64* w1I = (const u64*)w1f;
    float* b0s = sm + SM_B0;
    float* b1s = sm + SM_B1;
    float* fcw = sm + SM_FCW;
    float* fcb = sm + SM_FCB;
    float* dinT = sm + SM_DIN;
    float* h0A = sm + SM_H0;
    float* h0B = sm + SM_H0B;
    float* h1A = sm + SM_H1;
    float* h1B = sm + SM_H1B;

    const int tid = threadIdx.x;
    const int b0 = blockIdx.x * 32;
    const int wid = tid >> 5, lane = tid & 31;
    const int r0 = (lane >> 2) * 4;
    const int j2 = wid * 4 + (lane & 3);
    const int jcol = j2 * 2;

    // ---- load encoder weights, interleaved (w0 rows 0..63 only) ----
    for (int idx = tid; idx < HID * NG; idx += 256) {
        int k = idx >> 8, g = idx & 255;
        w0f[widx(k, g)] = eWhh0[g * HID + k];
        w1f[widx(k, g)] = eWih1[g * HID + k];
        w1f[widx(k + HID, g)] = eWhh1[g * HID + k];
    }
    if (tid < NG) b1s[tid] = ebih1[tid] + ebhh1[tid];
    for (int idx = tid; idx < HID * 32; idx += 256) { h1A[idx] = 0.f; h1B[idx] = 0.f; }
    __syncthreads();

    float c0[4][2] = {{0,0},{0,0},{0,0},{0,0}};
    float c1[4][2] = {{0,0},{0,0},{0,0},{0,0}};
    u64 acc0[4][4], acc1[4][4];
    u64 xg[4][4];
    float hn[4][2];

    // ================= encoder: fused L1(t) + L0(t+1), 1 barrier/iter =======
    // h0(t) lives in buf[t&1] (A=even), h1(t) in buf1[t&1] (A=even).
    // Prologue: h0(0) = cell(xg(0), c0=0)  (enc h0 init is zero)
    {
#pragma unroll
        for (int rr = 0; rr < 4; rr++) {
            const float* src =
                g_xg0 + ((size_t)(b0 + r0 + rr) * T_ENC + 0) * NG + jcol;
#pragma unroll
            for (int blk = 0; blk < 4; blk++)
                acc0[rr][blk] = *(const u64*)(src + blk * 64);
        }
        cell_update(acc0, c0, hn);
        h_store(hn, h0A, r0, jcol);       // h0(0) -> buf[0] = A
        __syncthreads();
    }

    // iteration i computes h1(i) and h0(i+1), i = 0..T_ENC-2
    for (int i = 0; i < T_ENC - 1; i++) {
        float* h0rd = (i & 1) ? h0B : h0A;     // h0(i)
        float* h0wr = (i & 1) ? h0A : h0B;     // h0(i+1) -> buf[(i+1)&1]
        float* h1rd = (i & 1) ? h1A : h1B;     // h1(i-1)  (h1(-1)=zeros in B)
        float* h1wr = (i & 1) ? h1B : h1A;     // h1(i) -> buf1[i&1]

        // acc1 = b1 (L1 gates), acc0 = 0 (L0(i+1) partial)
#pragma unroll
        for (int blk = 0; blk < 4; blk++) {
            u64 b = *(const u64*)&b1s[blk * 64 + jcol];
#pragma unroll
            for (int rr = 0; rr < 4; rr++) { acc1[rr][blk] = b; acc0[rr][blk] = 0ull; }
        }

        // k 0..63: h0(i) feeds BOTH Wih1 (acc1) and Whh0 (acc0)
        gemm2i_dual(acc1, acc0, h0rd, w1I, w0I, r0, j2);

        // prefetch xg(i+1); covered by the next 64-iter GEMM
#pragma unroll
        for (int rr = 0; rr < 4; rr++) {
            const float* src =
                g_xg0 + ((size_t)(b0 + r0 + rr) * T_ENC + (i + 1)) * NG + jcol;
#pragma unroll
            for (int blk = 0; blk < 4; blk++)
                xg[rr][blk] = *(const u64*)(src + blk * 64);
        }

        // k 64..127: h1(i-1) feeds Whh1 (acc1)
        gemm2i(acc1, h1rd, w1I + HID * 32 * 4, HID, r0, j2);

        // updates + stores (WAR-safe: both stores target non-read buffers)
        cell_update(acc1, c1, hn);
        h_store(hn, h1wr, r0, jcol);           // h1(i)

#pragma unroll
        for (int rr = 0; rr < 4; rr++)
#pragma unroll
            for (int blk = 0; blk < 4; blk++) add2(acc0[rr][blk], xg[rr][blk]);
        cell_update(acc0, c0, hn);
        h_store(hn, h0wr, r0, jcol);           // h0(i+1)

        __syncthreads();                        // publish h1(i), h0(i+1)
    }

    // Epilogue: L1(T-1).  h0(167) in buf[1]=B, h1(166) in buf1[0]=A
    {
#pragma unroll
        for (int blk = 0; blk < 4; blk++) {
            u64 b = *(const u64*)&b1s[blk * 64 + jcol];
#pragma unroll
            for (int rr = 0; rr < 4; rr++) acc1[rr][blk] = b;
        }
        gemm2i(acc1, h0B, w1I, HID, r0, j2);
        gemm2i(acc1, h1A, w1I + HID * 32 * 4, HID, r0, j2);
        cell_update(acc1, c1, hn);
        __syncthreads();                        // all reads of h1A done
        h_store(hn, h1B, r0, jcol);            // h1(167) -> buf1[1]=B
        __syncthreads();
    }

    // Move final states into A buffers (decoder expects [h0A|h1A] contiguous)
    for (int idx = tid; idx < HID * 32; idx += 256) {
        h0A[idx] = h0B[idx];
        h1A[idx] = h1B[idx];
    }
    __syncthreads();

    // ---- swap in decoder weights (overwrites h0B/h1B overlay regions) ----
    for (int idx = tid; idx < NT * NG; idx += 256) {     // dec_Wih0 -> rows 0..7
        int k = idx >> 8, g = idx & 255;
        w0f[widx(k, g)] = dWih0[g * NT + k];
    }
    for (int idx = tid; idx < HID * NG; idx += 256) {
        int k = idx >> 8, g = idx & 255;
        w0f[widx(k + NT, g)] = dWhh0[g * HID + k];        // rows 8..71
        w1f[widx(k, g)] = dWih1[g * HID + k];
        w1f[widx(k + HID, g)] = dWhh1[g * HID + k];
    }
    if (tid < NG) {
        b0s[tid] = dbih0[tid] + dbhh0[tid];
        b1s[tid] = dbih1[tid] + dbhh1[tid];
    }
    for (int idx = tid; idx < HID * NT; idx += 256) {     // fc_W[o][j] -> fcw[j][o]
        int j = idx >> 3, o = idx & 7;
        fcw[idx] = fcW[o * HID + j];
    }
    if (tid < NT) fcb[tid] = fcBias[tid];
    for (int idx = tid; idx < NT * 32; idx += 256) dinT[idx] = 0.f;
    __syncthreads();

    // ================= decoder =================
    for (int s = 0; s < T_DEC; s++) {
        // layer 0: din (K=8) + h0 (K=64)
#pragma unroll
        for (int blk = 0; blk < 4; blk++) {
            u64 b = *(const u64*)&b0s[blk * 64 + jcol];
#pragma unroll
            for (int rr = 0; rr < 4; rr++) acc0[rr][blk] = b;
        }
        gemm2i(acc0, dinT, w0I, NT, r0, j2);
        gemm2i(acc0, h0A, w0I + NT * 32 * 4, HID, r0, j2);
        cell_update(acc0, c0, hn);
        __syncthreads();
        h_store(hn, h0A, r0, jcol);
        __syncthreads();

        // layer 1: [h0A|h1A] contiguous, K=128
#pragma unroll
        for (int blk = 0; blk < 4; blk++) {
            u64 b = *(const u64*)&b1s[blk * 64 + jcol];
#pragma unroll
            for (int rr = 0; rr < 4; rr++) acc1[rr][blk] = b;
        }
        gemm2i(acc1, h0A, w1I, 2 * HID, r0, j2);
        cell_update(acc1, c1, hn);
        __syncthreads();
        h_store(hn, h1A, r0, jcol);
        __syncthreads();                 // h1 visible to FC

        // FC: one (row, out) per thread; h1A transposed [j][row]
        {
            int r = tid >> 3, o = tid & 7;
            float a = fcb[o];
#pragma unroll 8
            for (int j = 0; j < HID; j++)
                a = fmaf(h1A[j * 32 + r], fcw[j * NT + o], a);
            out[((size_t)(b0 + r) * T_DEC + s) * NT + o] = a;
            dinT[o * 32 + r] = a;
        }
        __syncthreads();                 // dinT visible to next layer 0
    }
}

// ---------------------------------------------------------------------------
extern "C" void kernel_launch(void* const* d_in, const int* in_sizes, int n_in,
                              void* d_out, int out_size)
{
    const float* x     = (const float*)d_in[0];
    const float* eWih0 = (const float*)d_in[1];
    const float* eWhh0 = (const float*)d_in[2];
    const float* ebih0 = (const float*)d_in[3];
    const float* ebhh0 = (const float*)d_in[4];
    const float* eWih1 = (const float*)d_in[5];
    const float* eWhh1 = (const float*)d_in[6];
    const float* ebih1 = (const float*)d_in[7];
    const float* ebhh1 = (const float*)d_in[8];
    const float* dWih0 = (const float*)d_in[9];
    const float* dWhh0 = (const float*)d_in[10];
    const float* dbih0 = (const float*)d_in[11];
    const float* dbhh0 = (const float*)d_in[12];
    const float* dWih1 = (const float*)d_in[13];
    const float* dWhh1 = (const float*)d_in[14];
    const float* dbih1 = (const float*)d_in[15];
    const float* dbhh1 = (const float*)d_in[16];
    const float* fcW   = (const float*)d_in[17];
    const float* fcb   = (const float*)d_in[18];
    float* out = (float*)d_out;

    cudaFuncSetAttribute(seq2seq_kernel,
                         cudaFuncAttributeMaxDynamicSharedMemorySize, SMEM_BYTES);

    xg0_kernel<<<B_TOT / 32, 256>>>(x, eWih0, ebih0, ebhh0);
    seq2seq_kernel<<<B_TOT / 32, 256, SMEM_BYTES>>>(
        eWhh0, eWih1, eWhh1, ebih1, ebhh1,
        dWih0, dWhh0, dbih0, dbhh0, dWih1, dWhh1, dbih1, dbhh1,
        fcW, fcb, out);
}

// round 11
// speedup vs baseline: 2.2766x; 1.6760x over previous
#include <cuda_runtime.h>

#define B_TOT 4096
#define T_ENC 168
#define T_DEC 24
#define NF    32
#define NT    8
#define HID   64
#define NG    256   // 4*HID

// Phase-1 scratch: XG0[b][t][g] = x[b,t,:] @ Wih0^T + bih0 + bhh0  (704 MB)
__device__ float g_xg0[(size_t)B_TOT * T_ENC * NG];

typedef unsigned long long u64;
typedef unsigned int u32;

// ---------------------------------------------------------------------------
// packed fp32 helpers (phase 1) + activations
// ---------------------------------------------------------------------------
__device__ __forceinline__ u64 pack2(float v) {
    u64 r;
    u32 b = __float_as_uint(v);
    asm("mov.b64 %0, {%1, %2};" : "=l"(r) : "r"(b), "r"(b));
    return r;
}
__device__ __forceinline__ void fma2(u64& acc, u64 a, u64 b) {
    asm("fma.rn.f32x2 %0, %1, %2, %0;" : "+l"(acc) : "l"(a), "l"(b));
}
__device__ __forceinline__ float ftanh(float x) {      // MUFU.TANH
    float y;
    asm("tanh.approx.f32 %0, %1;" : "=f"(y) : "f"(x));
    return y;
}
__device__ __forceinline__ float fsig(float x) {       // 1 MUFU + 1 FMA
    return fmaf(ftanh(0.5f * x), 0.5f, 0.5f);
}
__device__ __forceinline__ u32 f2tf(float f) {         // fp32 -> tf32 bits
    u32 r;
    asm("cvt.rna.tf32.f32 %0, %1;" : "=r"(r) : "f"(f));
    return r;
}

// ---------------------------------------------------------------------------
// m16n8k4 tf32 mma:
//   A (16x4): a0=(row=groupID, k=tig), a1=(row=groupID+8, k=tig)
//   B (4x8):  b0=(k=tig, n=groupID)
//   C (16x8): c0=(g,2t) c1=(g,2t+1) c2=(g+8,2t) c3=(g+8,2t+1)
// ---------------------------------------------------------------------------
__device__ __forceinline__ void mma_k4(float* d, uint2 a, u32 b) {
    asm volatile(
        "mma.sync.aligned.m16n8k4.row.col.f32.tf32.tf32.f32 "
        "{%0,%1,%2,%3}, {%4,%5}, {%6}, {%0,%1,%2,%3};"
        : "+f"(d[0]), "+f"(d[1]), "+f"(d[2]), "+f"(d[3])
        : "r"(a.x), "r"(a.y), "r"(b));
}

// B-fragment scatter index for W[n][k]: kcblk = k/4 block, k4 = k%4.
// Layout per kcblk: [wq(8)][lane(32)][blk(4)] = 1024 u32.
__device__ __forceinline__ int wfidx4(int kcblk, int k4, int n) {
    int blk = n >> 6, wq = (n >> 3) & 7, gq = n & 7;
    int lane = (gq << 2) | k4;
    return ((kcblk * 8 + wq) * 32 + lane) * 4 + blk;
}

// GEMM over nkc k4-chunks. hf: A-frag buffer [kc][mt(2)][lane(32)][2].
__device__ __forceinline__ void gemm_mma(
    float acc[2][4][4], const u32* __restrict__ hf,
    const u32* __restrict__ wf, int nkc, int lane, int w)
{
#pragma unroll
    for (int kc = 0; kc < nkc; kc++) {
        uint2 A0 = *(const uint2*)(hf + kc * 128 + lane * 2);
        uint2 A1 = *(const uint2*)(hf + kc * 128 + 64 + lane * 2);
        uint4 B = *(const uint4*)(wf + (kc * 8 + w) * 128 + lane * 4);
        mma_k4(acc[0][0], A0, B.x);
        mma_k4(acc[0][1], A0, B.y);
        mma_k4(acc[0][2], A0, B.z);
        mma_k4(acc[0][3], A0, B.w);
        mma_k4(acc[1][0], A1, B.x);
        mma_k4(acc[1][1], A1, B.y);
        mma_k4(acc[1][2], A1, B.z);
        mma_k4(acc[1][3], A1, B.w);
    }
}

// PyTorch gate order: blk0=i, blk1=f, blk2=g, blk3=o.
__device__ __forceinline__ void cell_mma(
    const float acc[2][4][4], float c[2][4], float hn[2][4])
{
#pragma unroll
    for (int mt = 0; mt < 2; mt++)
#pragma unroll
        for (int d = 0; d < 4; d++) {
            float ig = fsig(acc[mt][0][d]);
            float fg = fsig(acc[mt][1][d]);
            float gg = ftanh(acc[mt][2][d]);
            float og = fsig(acc[mt][3][d]);
            float cn = fmaf(fg, c[mt][d], ig * gg);
            c[mt][d] = cn;
            hn[mt][d] = og * ftanh(cn);
        }
}

// Scatter hn into A-fragment layout (tf32).
__device__ __forceinline__ void hstore_frag(
    const float hn[2][4], u32* __restrict__ dst, int lane, int w)
{
    int g = lane >> 2, tl = lane & 3;
#pragma unroll
    for (int mt = 0; mt < 2; mt++)
#pragma unroll
        for (int d = 0; d < 4; d++) {
            int rh = d >> 1, cc = d & 1;
            int jj = 2 * tl + cc;
            int kc = 2 * w + (jj >> 2);
            int lane2 = (g << 2) | (jj & 3);
            dst[kc * 128 + mt * 64 + lane2 * 2 + rh] = f2tf(hn[mt][d]);
        }
}

// ---------------------------------------------------------------------------
// Phase 1: persistent XG0 kernel (R6/R8-proven, fp32 FMA2). grid=128, 256 thr.
// ---------------------------------------------------------------------------
__device__ __forceinline__ void gemm2(
    u64 acc[4][4], const float* __restrict__ hT, int hstride,
    const float* __restrict__ ws, int wstride, int K, int r0, int jcol)
{
#pragma unroll 2
    for (int k = 0; k < K; k += 4) {
#pragma unroll
        for (int kk = 0; kk < 4; kk++) {
            float4 a = *(const float4*)&hT[(k + kk) * hstride + r0];
            const float* wr = ws + (k + kk) * wstride + jcol;
            u64 w0 = *(const u64*)(wr);
            u64 w1 = *(const u64*)(wr + 64);
            u64 w2 = *(const u64*)(wr + 128);
            u64 w3 = *(const u64*)(wr + 192);
            u64 h0 = pack2(a.x), h1 = pack2(a.y), h2 = pack2(a.z), h3 = pack2(a.w);
            fma2(acc[0][0], h0, w0); fma2(acc[0][1], h0, w1);
            fma2(acc[0][2], h0, w2); fma2(acc[0][3], h0, w3);
            fma2(acc[1][0], h1, w0); fma2(acc[1][1], h1, w1);
            fma2(acc[1][2], h1, w2); fma2(acc[1][3], h1, w3);
            fma2(acc[2][0], h2, w0); fma2(acc[2][1], h2, w1);
            fma2(acc[2][2], h2, w2); fma2(acc[2][3], h2, w3);
            fma2(acc[3][0], h3, w0); fma2(acc[3][1], h3, w1);
            fma2(acc[3][2], h3, w2); fma2(acc[3][3], h3, w3);
        }
    }
}

#define XS_STRIDE 36
__global__ void __launch_bounds__(256) xg0_kernel(
    const float* __restrict__ x, const float* __restrict__ Wih0,
    const float* __restrict__ bih0, const float* __restrict__ bhh0)
{
    __shared__ float xs[NF * XS_STRIDE];
    __shared__ float ws[NF * 258];
    __shared__ float bs[NG];

    const int tid = threadIdx.x;
    const int b0 = blockIdx.x * 32;

    for (int idx = tid; idx < NG * NF; idx += 256) {
        int k = idx & 31, g = idx >> 5;
        ws[k * 258 + g] = Wih0[idx];
    }
    if (tid < NG) bs[tid] = bih0[tid] + bhh0[tid];

    const int wid = tid >> 5, lane = tid & 31;
    const int r0 = (lane >> 2) * 4;
    const int jcol = wid * 8 + (lane & 3) * 2;

    const int xr = tid >> 3;
    const int k4 = (tid & 7) * 4;

    float4 xv = *(const float4*)(x + ((size_t)(b0 + xr) * T_ENC + 0) * NF + k4);
    __syncthreads();

    for (int t = 0; t < T_ENC; t++) {
        xs[(k4 + 0) * XS_STRIDE + xr] = xv.x;
        xs[(k4 + 1) * XS_STRIDE + xr] = xv.y;
        xs[(k4 + 2) * XS_STRIDE + xr] = xv.z;
        xs[(k4 + 3) * XS_STRIDE + xr] = xv.w;
        __syncthreads();

        if (t + 1 < T_ENC)
            xv = *(const float4*)(x + ((size_t)(b0 + xr) * T_ENC + t + 1) * NF + k4);

        u64 acc[4][4];
#pragma unroll
        for (int blk = 0; blk < 4; blk++) {
            u64 b = *(const u64*)&bs[blk * 64 + jcol];
#pragma unroll
            for (int rr = 0; rr < 4; rr++) acc[rr][blk] = b;
        }
        gemm2(acc, xs, XS_STRIDE, ws, 258, NF, r0, jcol);

#pragma unroll
        for (int rr = 0; rr < 4; rr++) {
            float* dst = g_xg0 + ((size_t)(b0 + r0 + rr) * T_ENC + t) * NG + jcol;
#pragma unroll
            for (int blk = 0; blk < 4; blk++)
                *(u64*)(dst + blk * 64) = acc[rr][blk];
        }
        __syncthreads();
    }
}

// ---------------------------------------------------------------------------
// Phase 2 smem (floats). Weights in k4 B-frag layout; h in k4 A-frag layout.
// w0: 18 kcblk * 1024 (enc uses 0..15; dec: Wih0=0..1, Whh0=2..17)
// w1: 32 kcblk * 1024 (Wih1=0..15, Whh1=16..31)
// ---------------------------------------------------------------------------
#define SM_W0    0                      // 18432
#define SM_W1    (SM_W0 + 18 * 1024)    // 32768
#define SM_HF0A  (SM_W1 + 32 * 1024)    // 2048
#define SM_HF0B  (SM_HF0A + 2048)       // 2048 (decoder: h1plain overlay)
#define SM_HF1A  (SM_HF0B + 2048)       // 2048
#define SM_DINA  (SM_HF1A + 2048)       // 256
#define SM_TOTAL (SM_DINA + 256)        // 57600 fl = 230400 B
#define SMEM_BYTES (SM_TOTAL * 4)

__global__ void __launch_bounds__(256, 1) seq2seq_kernel(
    const float* __restrict__ eWhh0,
    const float* __restrict__ eWih1, const float* __restrict__ eWhh1,
    const float* __restrict__ ebih1, const float* __restrict__ ebhh1,
    const float* __restrict__ dWih0, const float* __restrict__ dWhh0,
    const float* __restrict__ dbih0, const float* __restrict__ dbhh0,
    const float* __restrict__ dWih1, const float* __restrict__ dWhh1,
    const float* __restrict__ dbih1, const float* __restrict__ dbhh1,
    const float* __restrict__ fcW, const float* __restrict__ fcBias,
    float* __restrict__ out)
{
    extern __shared__ float sm[];
    u32* w0u  = (u32*)(sm + SM_W0);
    u32* w1u  = (u32*)(sm + SM_W1);
    u32* hF0A = (u32*)(sm + SM_HF0A);
    u32* hF0B = (u32*)(sm + SM_HF0B);
    u32* hF1A = (u32*)(sm + SM_HF1A);
    u32* dinA = (u32*)(sm + SM_DINA);
    float* h1plain = sm + SM_HF0B;      // decoder-only overlay of hF0B

    const int tid = threadIdx.x;
    const int b0 = blockIdx.x * 32;
    const int w = tid >> 5, lane = tid & 31;
    const int g = lane >> 2, tl = lane & 3;
    const int colb = w * 8 + 2 * tl;    // base output column of this thread

    // ---- biases into registers ----
    // b1v: ENCODER L1.  d1v: DECODER L1 (distinct! R9/R10 bug).  b0v: dec L0.
    float2 b1v[4], d1v[4], b0v[4];
#pragma unroll
    for (int blk = 0; blk < 4; blk++) {
        int cg = blk * 64 + colb;
        b1v[blk] = make_float2(ebih1[cg] + ebhh1[cg], ebih1[cg + 1] + ebhh1[cg + 1]);
        d1v[blk] = make_float2(dbih1[cg] + dbhh1[cg], dbih1[cg + 1] + dbhh1[cg + 1]);
        b0v[blk] = make_float2(dbih0[cg] + dbhh0[cg], dbih0[cg + 1] + dbhh0[cg + 1]);
    }
    float fcbr = fcBias[tid & 7];

    // ---- encoder weight fill (B-frag layout, tf32) ----
    for (int idx = tid; idx < HID * NG; idx += 256) {
        int k = idx >> 8, n = idx & 255;
        w0u[wfidx4(k >> 2, k & 3, n)]        = f2tf(eWhh0[n * HID + k]);
        w1u[wfidx4(k >> 2, k & 3, n)]        = f2tf(eWih1[n * HID + k]);
        w1u[wfidx4(16 + (k >> 2), k & 3, n)] = f2tf(eWhh1[n * HID + k]);
    }
    for (int idx = tid; idx < 2048; idx += 256) {
        hF0A[idx] = 0u; hF0B[idx] = 0u; hF1A[idx] = 0u;
    }
    __syncthreads();

    float c0[2][4] = {}, c1[2][4] = {};
    float acc[2][4][4], hn[2][4];
    float2 xgv[2][2][4];

    // ================= encoder (2 barriers/step, h0 double-buffered) ========
    for (int t = 0; t < T_ENC; t++) {
        u32* h0rd = (t & 1) ? hF0B : hF0A;
        u32* h0wr = (t & 1) ? hF0A : hF0B;

        // prefetch xg(t)
#pragma unroll
        for (int mt = 0; mt < 2; mt++)
#pragma unroll
            for (int rh = 0; rh < 2; rh++) {
                const float* srow = g_xg0 +
                    ((size_t)(b0 + mt * 16 + rh * 8 + g) * T_ENC + t) * NG + colb;
#pragma unroll
                for (int blk = 0; blk < 4; blk++)
                    xgv[mt][rh][blk] = *(const float2*)(srow + blk * 64);
            }

        // L0: acc = Whh0 x h0(t-1) + xg(t)
#pragma unroll
        for (int mt = 0; mt < 2; mt++)
#pragma unroll
            for (int blk = 0; blk < 4; blk++)
#pragma unroll
                for (int d = 0; d < 4; d++) acc[mt][blk][d] = 0.f;
        gemm_mma(acc, h0rd, w0u, 16, lane, w);
#pragma unroll
        for (int mt = 0; mt < 2; mt++)
#pragma unroll
            for (int blk = 0; blk < 4; blk++) {
                acc[mt][blk][0] += xgv[mt][0][blk].x;
                acc[mt][blk][1] += xgv[mt][0][blk].y;
                acc[mt][blk][2] += xgv[mt][1][blk].x;
                acc[mt][blk][3] += xgv[mt][1][blk].y;
            }
        cell_mma(acc, c0, hn);
        hstore_frag(hn, h0wr, lane, w);         // WAR-safe: alternate buffer
        __syncthreads();                         // publish h0(t) (+ h1(t-1))

        // L1: b1 + Wih1 x h0(t) + Whh1 x h1(t-1)
#pragma unroll
        for (int mt = 0; mt < 2; mt++)
#pragma unroll
            for (int blk = 0; blk < 4; blk++) {
                acc[mt][blk][0] = b1v[blk].x; acc[mt][blk][1] = b1v[blk].y;
                acc[mt][blk][2] = b1v[blk].x; acc[mt][blk][3] = b1v[blk].y;
            }
        gemm_mma(acc, h0wr, w1u, 16, lane, w);
        gemm_mma(acc, hF1A, w1u + 16 * 1024, 16, lane, w);
        cell_mma(acc, c1, hn);
        __syncthreads();                         // all h1 reads done
        hstore_frag(hn, hF1A, lane, w);
        // RAW for next step's h1 read covered by next step's first barrier
    }
    __syncthreads();                             // weights about to change

    // ---- decoder weight fill ----
    for (int idx = tid; idx < NT * NG; idx += 256) {      // Wih0: kcblk 0..1
        int k = idx >> 8, n = idx & 255;
        w0u[wfidx4(k >> 2, k & 3, n)] = f2tf(dWih0[n * NT + k]);
    }
    for (int idx = tid; idx < HID * NG; idx += 256) {
        int k = idx >> 8, n = idx & 255;
        w0u[wfidx4(2 + (k >> 2), k & 3, n)]  = f2tf(dWhh0[n * HID + k]);
        w1u[wfidx4(k >> 2, k & 3, n)]        = f2tf(dWih1[n * HID + k]);
        w1u[wfidx4(16 + (k >> 2), k & 3, n)] = f2tf(dWhh1[n * HID + k]);
    }
    for (int idx = tid; idx < 256; idx += 256) dinA[idx] = 0u;
    __syncthreads();

    // ================= decoder =================
    for (int s = 0; s < T_DEC; s++) {
        // L0: b0 + Wih0 x din (2 chunks) + Whh0 x h0 (16 chunks)
#pragma unroll
        for (int mt = 0; mt < 2; mt++)
#pragma unroll
            for (int blk = 0; blk < 4; blk++) {
                acc[mt][blk][0] = b0v[blk].x; acc[mt][blk][1] = b0v[blk].y;
                acc[mt][blk][2] = b0v[blk].x; acc[mt][blk][3] = b0v[blk].y;
            }
        gemm_mma(acc, dinA, w0u, 2, lane, w);
        gemm_mma(acc, hF0A, w0u + 2 * 1024, 16, lane, w);
        cell_mma(acc, c0, hn);
        __syncthreads();
        hstore_frag(hn, hF0A, lane, w);
        __syncthreads();

        // L1: d1 (DECODER bias) + Wih1 x h0 + Whh1 x h1
#pragma unroll
        for (int mt = 0; mt < 2; mt++)
#pragma unroll
            for (int blk = 0; blk < 4; blk++) {
                acc[mt][blk][0] = d1v[blk].x; acc[mt][blk][1] = d1v[blk].y;
                acc[mt][blk][2] = d1v[blk].x; acc[mt][blk][3] = d1v[blk].y;
            }
        gemm_mma(acc, hF0A, w1u, 16, lane, w);
        gemm_mma(acc, hF1A, w1u + 16 * 1024, 16, lane, w);
        cell_mma(acc, c1, hn);
        __syncthreads();
        hstore_frag(hn, hF1A, lane, w);
        // plain fp32 h1 copy for the FC
#pragma unroll
        for (int mt = 0; mt < 2; mt++)
#pragma unroll
            for (int d = 0; d < 4; d++) {
                int r = mt * 16 + (d >> 1) * 8 + g;
                int j = colb + (d & 1);
                h1plain[j * 32 + r] = hn[mt][d];
            }
        __syncthreads();                 // h1plain visible to FC

        // FC: one (row, out) per thread
        {
            int r = tid >> 3, o = tid & 7;
            float a = fcbr;
#pragma unroll 8
            for (int j = 0; j < HID; j++)
                a = fmaf(h1plain[j * 32 + r], fcW[o * HID + j], a);
            out[((size_t)(b0 + r) * T_DEC + s) * NT + o] = a;
            // scatter into din A-fragment slot (kc = o>>2)
            int lane2 = ((r & 7) << 2) | (o & 3);
            dinA[(o >> 2) * 128 + (r >> 4) * 64 + lane2 * 2 + ((r >> 3) & 1)] = f2tf(a);
        }
        __syncthreads();                 // dinA visible to next L0
    }
}

// ---------------------------------------------------------------------------
extern "C" void kernel_launch(void* const* d_in, const int* in_sizes, int n_in,
                              void* d_out, int out_size)
{
    const float* x     = (const float*)d_in[0];
    const float* eWih0 = (const float*)d_in[1];
    const float* eWhh0 = (const float*)d_in[2];
    const float* ebih0 = (const float*)d_in[3];
    const float* ebhh0 = (const float*)d_in[4];
    const float* eWih1 = (const float*)d_in[5];
    const float* eWhh1 = (const float*)d_in[6];
    const float* ebih1 = (const float*)d_in[7];
    const float* ebhh1 = (const float*)d_in[8];
    const float* dWih0 = (const float*)d_in[9];
    const float* dWhh0 = (const float*)d_in[10];
    const float* dbih0 = (const float*)d_in[11];
    const float* dbhh0 = (const float*)d_in[12];
    const float* dWih1 = (const float*)d_in[13];
    const float* dWhh1 = (const float*)d_in[14];
    const float* dbih1 = (const float*)d_in[15];
    const float* dbhh1 = (const float*)d_in[16];
    const float* fcW   = (const float*)d_in[17];
    const float* fcb   = (const float*)d_in[18];
    float* out = (float*)d_out;

    cudaFuncSetAttribute(seq2seq_kernel,
                         cudaFuncAttributeMaxDynamicSharedMemorySize, SMEM_BYTES);

    xg0_kernel<<<B_TOT / 32, 256>>>(x, eWih0, ebih0, ebhh0);
    seq2seq_kernel<<<B_TOT / 32, 256, SMEM_BYTES>>>(
        eWhh0, eWih1, eWhh1, ebih1, ebhh1,
        dWih0, dWhh0, dbih0, dbhh0, dWih1, dWhh1, dbih1, dbhh1,
        fcW, fcb, out);
}

// round 12
// speedup vs baseline: 2.9598x; 1.3001x over previous
#include <cuda_runtime.h>

#define B_TOT 4096
#define T_ENC 168
#define T_DEC 24
#define NF    32
#define NT    8
#define HID   64
#define NG    256   // 4*HID

// Phase-1 scratch: XG0[b][t][g] = x[b,t,:] @ Wih0^T + bih0 + bhh0  (704 MB)
__device__ float g_xg0[(size_t)B_TOT * T_ENC * NG];

typedef unsigned long long u64;
typedef unsigned int u32;

// ---------------------------------------------------------------------------
// activations + tf32 convert
// ---------------------------------------------------------------------------
__device__ __forceinline__ float ftanh(float x) {      // MUFU.TANH
    float y;
    asm("tanh.approx.f32 %0, %1;" : "=f"(y) : "f"(x));
    return y;
}
__device__ __forceinline__ float fsig(float x) {       // 1 MUFU + 1 FMA
    return fmaf(ftanh(0.5f * x), 0.5f, 0.5f);
}
__device__ __forceinline__ u32 f2tf(float f) {         // fp32 -> tf32 bits
    u32 r;
    asm("cvt.rna.tf32.f32 %0, %1;" : "=r"(r) : "f"(f));
    return r;
}

// ---------------------------------------------------------------------------
// m16n8k8 tf32 mma. Fragments = concatenation of two validated k4 chunks:
//   A: a0=(g,tig) a1=(g+8,tig) from chunk kc; a2,a3 same from chunk kc+1
//   B: b0=(tig,g) chunk kc; b1 chunk kc+1
//   C: c0=(g,2t) c1=(g,2t+1) c2=(g+8,2t) c3=(g+8,2t+1)
// ---------------------------------------------------------------------------
__device__ __forceinline__ void mma_k8(float* d, uint4 a, u32 b0, u32 b1) {
    asm volatile(
        "mma.sync.aligned.m16n8k8.row.col.f32.tf32.tf32.f32 "
        "{%0,%1,%2,%3}, {%4,%5,%6,%7}, {%8,%9}, {%0,%1,%2,%3};"
        : "+f"(d[0]), "+f"(d[1]), "+f"(d[2]), "+f"(d[3])
        : "r"(a.x), "r"(a.y), "r"(a.z), "r"(a.w), "r"(b0), "r"(b1));
}

// B-fragment scatter index for W[n][k] (k4-chunk layout, R11-validated):
// kcblk = k/4, k4 = k%4. Per kcblk: [wq(8)][lane(32)][blk(4)] = 1024 u32.
__device__ __forceinline__ int wfidx4(int kcblk, int k4, int n) {
    int blk = n >> 6, wq = (n >> 3) & 7, gq = n & 7;
    int lane = (gq << 2) | k4;
    return ((kcblk * 8 + wq) * 32 + lane) * 4 + blk;
}

// GEMM over nkc k4-chunks (nkc even), issued as k8 over chunk pairs.
// hf: A-frag buffer [kc][mt(2)][lane(32)][2]. wf: B-frag buffer.
__device__ __forceinline__ void gemm_mma(
    float acc[2][4][4], const u32* __restrict__ hf,
    const u32* __restrict__ wf, int nkc, int lane, int w)
{
#pragma unroll
    for (int kc = 0; kc < nkc; kc += 2) {
        uint2 a0lo = *(const uint2*)(hf + kc * 128 + lane * 2);
        uint2 a0hi = *(const uint2*)(hf + (kc + 1) * 128 + lane * 2);
        uint2 a1lo = *(const uint2*)(hf + kc * 128 + 64 + lane * 2);
        uint2 a1hi = *(const uint2*)(hf + (kc + 1) * 128 + 64 + lane * 2);
        uint4 A0 = make_uint4(a0lo.x, a0lo.y, a0hi.x, a0hi.y);
        uint4 A1 = make_uint4(a1lo.x, a1lo.y, a1hi.x, a1hi.y);
        uint4 Bx = *(const uint4*)(wf + (kc * 8 + w) * 128 + lane * 4);
        uint4 By = *(const uint4*)(wf + ((kc + 1) * 8 + w) * 128 + lane * 4);
        mma_k8(acc[0][0], A0, Bx.x, By.x);
        mma_k8(acc[0][1], A0, Bx.y, By.y);
        mma_k8(acc[0][2], A0, Bx.z, By.z);
        mma_k8(acc[0][3], A0, Bx.w, By.w);
        mma_k8(acc[1][0], A1, Bx.x, By.x);
        mma_k8(acc[1][1], A1, Bx.y, By.y);
        mma_k8(acc[1][2], A1, Bx.z, By.z);
        mma_k8(acc[1][3], A1, Bx.w, By.w);
    }
}

// PyTorch gate order: blk0=i, blk1=f, blk2=g, blk3=o.
__device__ __forceinline__ void cell_mma(
    const float acc[2][4][4], float c[2][4], float hn[2][4])
{
#pragma unroll
    for (int mt = 0; mt < 2; mt++)
#pragma unroll
        for (int d = 0; d < 4; d++) {
            float ig = fsig(acc[mt][0][d]);
            float fg = fsig(acc[mt][1][d]);
            float gg = ftanh(acc[mt][2][d]);
            float og = fsig(acc[mt][3][d]);
            float cn = fmaf(fg, c[mt][d], ig * gg);
            c[mt][d] = cn;
            hn[mt][d] = og * ftanh(cn);
        }
}

// Scatter hn into A-fragment layout (tf32). (R11-validated)
__device__ __forceinline__ void hstore_frag(
    const float hn[2][4], u32* __restrict__ dst, int lane, int w)
{
    int g = lane >> 2, tl = lane & 3;
#pragma unroll
    for (int mt = 0; mt < 2; mt++)
#pragma unroll
        for (int d = 0; d < 4; d++) {
            int rh = d >> 1, cc = d & 1;
            int jj = 2 * tl + cc;
            int kc = 2 * w + (jj >> 2);
            int lane2 = (g << 2) | (jj & 3);
            dst[kc * 128 + mt * 64 + lane2 * 2 + rh] = f2tf(hn[mt][d]);
        }
}

// ---------------------------------------------------------------------------
// Phase 1: XG0 via tf32 MMA. grid=128 persistent, 256 threads.
// Wih0 in B-frag (32 KB), x staged per step into double-buffered A-frag.
// ---------------------------------------------------------------------------
__global__ void __launch_bounds__(256) xg0_kernel(
    const float* __restrict__ x, const float* __restrict__ Wih0,
    const float* __restrict__ bih0, const float* __restrict__ bhh0)
{
    __shared__ u32 wfr[8 * 1024];       // Wih0 B-frag, 32 KB
    __shared__ u32 xfr[2][8 * 128];     // x A-frag, double-buffered, 2 x 4 KB

    const int tid = threadIdx.x;
    const int b0 = blockIdx.x * 32;
    const int w = tid >> 5, lane = tid & 31;
    const int g = lane >> 2, tl = lane & 3;
    const int colb = w * 8 + 2 * tl;

    // Wih0[n][k] -> B-frag (coalesced LDG over k)
    for (int idx = tid; idx < NG * NF; idx += 256) {
        int n = idx >> 5, k = idx & 31;
        wfr[wfidx4(k >> 2, k & 3, n)] = f2tf(Wih0[idx]);
    }
    float2 bv[4];
#pragma unroll
    for (int blk = 0; blk < 4; blk++) {
        int cg = blk * 64 + colb;
        bv[blk] = make_float2(bih0[cg] + bhh0[cg], bih0[cg + 1] + bhh0[cg + 1]);
    }

    // x staging: thread owns row xr = tid>>3, feature chunk kc = tid&7
    const int xr = tid >> 3;
    const int kc = tid & 7;
    const int xmt = xr >> 4, xrr = xr & 15;
    const int xword = xrr >> 3, xl8 = xrr & 7;
    const u32 xbase = kc * 128 + xmt * 64;

    float4 xv = *(const float4*)(x + ((size_t)(b0 + xr) * T_ENC + 0) * NF + kc * 4);
    __syncthreads();                    // wfr ready

    for (int t = 0; t < T_ENC; t++) {
        u32* xf = xfr[t & 1];
        xf[xbase + ((xl8 << 2) | 0) * 2 + xword] = f2tf(xv.x);
        xf[xbase + ((xl8 << 2) | 1) * 2 + xword] = f2tf(xv.y);
        xf[xbase + ((xl8 << 2) | 2) * 2 + xword] = f2tf(xv.z);
        xf[xbase + ((xl8 << 2) | 3) * 2 + xword] = f2tf(xv.w);
        if (t + 1 < T_ENC)
            xv = *(const float4*)(x + ((size_t)(b0 + xr) * T_ENC + t + 1) * NF + kc * 4);
        __syncthreads();                // xf ready (WAR safe via double buffer)

        float acc[2][4][4];
#pragma unroll
        for (int mt = 0; mt < 2; mt++)
#pragma unroll
            for (int blk = 0; blk < 4; blk++) {
                acc[mt][blk][0] = bv[blk].x; acc[mt][blk][1] = bv[blk].y;
                acc[mt][blk][2] = bv[blk].x; acc[mt][blk][3] = bv[blk].y;
            }
        gemm_mma(acc, xf, wfr, 8, lane, w);

#pragma unroll
        for (int mt = 0; mt < 2; mt++)
#pragma unroll
            for (int rh = 0; rh < 2; rh++) {
                float* dst = g_xg0 +
                    ((size_t)(b0 + mt * 16 + rh * 8 + g) * T_ENC + t) * NG + colb;
#pragma unroll
                for (int blk = 0; blk < 4; blk++)
                    *(float2*)(dst + blk * 64) =
                        make_float2(acc[mt][blk][rh * 2], acc[mt][blk][rh * 2 + 1]);
            }
    }
}

// ---------------------------------------------------------------------------
// Phase 2 smem (floats). Weights in k4 B-frag layout; h in k4 A-frag layout.
// w0: 18 kcblk (enc uses 0..15; dec: Wih0=0..1, Whh0=2..17)
// w1: 32 kcblk (Wih1=0..15, Whh1=16..31)
// ---------------------------------------------------------------------------
#define SM_W0    0                      // 18432
#define SM_W1    (SM_W0 + 18 * 1024)    // 32768
#define SM_HF0A  (SM_W1 + 32 * 1024)    // 2048
#define SM_HF0B  (SM_HF0A + 2048)       // 2048 (decoder: h1plain overlay)
#define SM_HF1A  (SM_HF0B + 2048)       // 2048
#define SM_DINA  (SM_HF1A + 2048)       // 256
#define SM_TOTAL (SM_DINA + 256)        // 57600 fl = 230400 B
#define SMEM_BYTES (SM_TOTAL * 4)

__global__ void __launch_bounds__(256, 1) seq2seq_kernel(
    const float* __restrict__ eWhh0,
    const float* __restrict__ eWih1, const float* __restrict__ eWhh1,
    const float* __restrict__ ebih1, const float* __restrict__ ebhh1,
    const float* __restrict__ dWih0, const float* __restrict__ dWhh0,
    const float* __restrict__ dbih0, const float* __restrict__ dbhh0,
    const float* __restrict__ dWih1, const float* __restrict__ dWhh1,
    const float* __restrict__ dbih1, const float* __restrict__ dbhh1,
    const float* __restrict__ fcW, const float* __restrict__ fcBias,
    float* __restrict__ out)
{
    extern __shared__ float sm[];
    u32* w0u  = (u32*)(sm + SM_W0);
    u32* w1u  = (u32*)(sm + SM_W1);
    u32* hF0A = (u32*)(sm + SM_HF0A);
    u32* hF0B = (u32*)(sm + SM_HF0B);
    u32* hF1A = (u32*)(sm + SM_HF1A);
    u32* dinA = (u32*)(sm + SM_DINA);
    float* h1plain = sm + SM_HF0B;      // decoder-only overlay of hF0B

    const int tid = threadIdx.x;
    const int b0 = blockIdx.x * 32;
    const int w = tid >> 5, lane = tid & 31;
    const int g = lane >> 2, tl = lane & 3;
    const int colb = w * 8 + 2 * tl;

    // ---- biases into registers (enc L1, dec L1, dec L0 — all distinct) ----
    float2 b1v[4], d1v[4], b0v[4];
#pragma unroll
    for (int blk = 0; blk < 4; blk++) {
        int cg = blk * 64 + colb;
        b1v[blk] = make_float2(ebih1[cg] + ebhh1[cg], ebih1[cg + 1] + ebhh1[cg + 1]);
        d1v[blk] = make_float2(dbih1[cg] + dbhh1[cg], dbih1[cg + 1] + dbhh1[cg + 1]);
        b0v[blk] = make_float2(dbih0[cg] + dbhh0[cg], dbih0[cg + 1] + dbhh0[cg + 1]);
    }
    float fcbr = fcBias[tid & 7];

    // ---- encoder weight fill (B-frag layout, tf32) ----
    for (int idx = tid; idx < HID * NG; idx += 256) {
        int k = idx >> 8, n = idx & 255;
        w0u[wfidx4(k >> 2, k & 3, n)]        = f2tf(eWhh0[n * HID + k]);
        w1u[wfidx4(k >> 2, k & 3, n)]        = f2tf(eWih1[n * HID + k]);
        w1u[wfidx4(16 + (k >> 2), k & 3, n)] = f2tf(eWhh1[n * HID + k]);
    }
    for (int idx = tid; idx < 2048; idx += 256) {
        hF0A[idx] = 0u; hF0B[idx] = 0u; hF1A[idx] = 0u;
    }
    __syncthreads();

    float c0[2][4] = {}, c1[2][4] = {};
    float acc[2][4][4], hn[2][4];
    float2 xgv[2][2][4];

    // ================= encoder (2 barriers/step, h0 double-buffered) ========
    for (int t = 0; t < T_ENC; t++) {
        u32* h0rd = (t & 1) ? hF0B : hF0A;
        u32* h0wr = (t & 1) ? hF0A : hF0B;

        // prefetch xg(t)
#pragma unroll
        for (int mt = 0; mt < 2; mt++)
#pragma unroll
            for (int rh = 0; rh < 2; rh++) {
                const float* srow = g_xg0 +
                    ((size_t)(b0 + mt * 16 + rh * 8 + g) * T_ENC + t) * NG + colb;
#pragma unroll
                for (int blk = 0; blk < 4; blk++)
                    xgv[mt][rh][blk] = *(const float2*)(srow + blk * 64);
            }

        // L0: acc = Whh0 x h0(t-1) + xg(t)
#pragma unroll
        for (int mt = 0; mt < 2; mt++)
#pragma unroll
            for (int blk = 0; blk < 4; blk++)
#pragma unroll
                for (int d = 0; d < 4; d++) acc[mt][blk][d] = 0.f;
        gemm_mma(acc, h0rd, w0u, 16, lane, w);
#pragma unroll
        for (int mt = 0; mt < 2; mt++)
#pragma unroll
            for (int blk = 0; blk < 4; blk++) {
                acc[mt][blk][0] += xgv[mt][0][blk].x;
                acc[mt][blk][1] += xgv[mt][0][blk].y;
                acc[mt][blk][2] += xgv[mt][1][blk].x;
                acc[mt][blk][3] += xgv[mt][1][blk].y;
            }
        cell_mma(acc, c0, hn);
        hstore_frag(hn, h0wr, lane, w);         // WAR-safe: alternate buffer
        __syncthreads();                         // publish h0(t) (+ h1(t-1))

        // L1: b1 + Wih1 x h0(t) + Whh1 x h1(t-1)
#pragma unroll
        for (int mt = 0; mt < 2; mt++)
#pragma unroll
            for (int blk = 0; blk < 4; blk++) {
                acc[mt][blk][0] = b1v[blk].x; acc[mt][blk][1] = b1v[blk].y;
                acc[mt][blk][2] = b1v[blk].x; acc[mt][blk][3] = b1v[blk].y;
            }
        gemm_mma(acc, h0wr, w1u, 16, lane, w);
        gemm_mma(acc, hF1A, w1u + 16 * 1024, 16, lane, w);
        cell_mma(acc, c1, hn);
        __syncthreads();                         // all h1 reads done
        hstore_frag(hn, hF1A, lane, w);
        // RAW for next step's h1 read covered by next step's first barrier
    }
    __syncthreads();                             // weights about to change

    // ---- decoder weight fill ----
    for (int idx = tid; idx < NT * NG; idx += 256) {      // Wih0: kcblk 0..1
        int k = idx >> 8, n = idx & 255;
        w0u[wfidx4(k >> 2, k & 3, n)] = f2tf(dWih0[n * NT + k]);
    }
    for (int idx = tid; idx < HID * NG; idx += 256) {
        int k = idx >> 8, n = idx & 255;
        w0u[wfidx4(2 + (k >> 2), k & 3, n)]  = f2tf(dWhh0[n * HID + k]);
        w1u[wfidx4(k >> 2, k & 3, n)]        = f2tf(dWih1[n * HID + k]);
        w1u[wfidx4(16 + (k >> 2), k & 3, n)] = f2tf(dWhh1[n * HID + k]);
    }
    for (int idx = tid; idx < 256; idx += 256) dinA[idx] = 0u;
    __syncthreads();

    // ================= decoder =================
    for (int s = 0; s < T_DEC; s++) {
        // L0: b0 + Wih0 x din (2 chunks) + Whh0 x h0 (16 chunks)
#pragma unroll
        for (int mt = 0; mt < 2; mt++)
#pragma unroll
            for (int blk = 0; blk < 4; blk++) {
                acc[mt][blk][0] = b0v[blk].x; acc[mt][blk][1] = b0v[blk].y;
                acc[mt][blk][2] = b0v[blk].x; acc[mt][blk][3] = b0v[blk].y;
            }
        gemm_mma(acc, dinA, w0u, 2, lane, w);
        gemm_mma(acc, hF0A, w0u + 2 * 1024, 16, lane, w);
        cell_mma(acc, c0, hn);
        __syncthreads();
        hstore_frag(hn, hF0A, lane, w);
        __syncthreads();

        // L1: d1 (decoder bias) + Wih1 x h0 + Whh1 x h1
#pragma unroll
        for (int mt = 0; mt < 2; mt++)
#pragma unroll
            for (int blk = 0; blk < 4; blk++) {
                acc[mt][blk][0] = d1v[blk].x; acc[mt][blk][1] = d1v[blk].y;
                acc[mt][blk][2] = d1v[blk].x; acc[mt][blk][3] = d1v[blk].y;
            }
        gemm_mma(acc, hF0A, w1u, 16, lane, w);
        gemm_mma(acc, hF1A, w1u + 16 * 1024, 16, lane, w);
        cell_mma(acc, c1, hn);
        __syncthreads();
        hstore_frag(hn, hF1A, lane, w);
        // plain fp32 h1 copy for the FC
#pragma unroll
        for (int mt = 0; mt < 2; mt++)
#pragma unroll
            for (int d = 0; d < 4; d++) {
                int r = mt * 16 + (d >> 1) * 8 + g;
                int j = colb + (d & 1);
                h1plain[j * 32 + r] = hn[mt][d];
            }
        __syncthreads();                 // h1plain visible to FC

        // FC: one (row, out) per thread
        {
            int r = tid >> 3, o = tid & 7;
            float a = fcbr;
#pragma unroll 8
            for (int j = 0; j < HID; j++)
                a = fmaf(h1plain[j * 32 + r], fcW[o * HID + j], a);
            out[((size_t)(b0 + r) * T_DEC + s) * NT + o] = a;
            // scatter into din A-fragment slot (kc = o>>2)
            int lane2 = ((r & 7) << 2) | (o & 3);
            dinA[(o >> 2) * 128 + (r >> 4) * 64 + lane2 * 2 + ((r >> 3) & 1)] = f2tf(a);
        }
        __syncthreads();                 // dinA visible to next L0
    }
}

// ---------------------------------------------------------------------------
extern "C" void kernel_launch(void* const* d_in, const int* in_sizes, int n_in,
                              void* d_out, int out_size)
{
    const float* x     = (const float*)d_in[0];
    const float* eWih0 = (const float*)d_in[1];
    const float* eWhh0 = (const float*)d_in[2];
    const float* ebih0 = (const float*)d_in[3];
    const float* ebhh0 = (const float*)d_in[4];
    const float* eWih1 = (const float*)d_in[5];
    const float* eWhh1 = (const float*)d_in[6];
    const float* ebih1 = (const float*)d_in[7];
    const float* ebhh1 = (const float*)d_in[8];
    const float* dWih0 = (const float*)d_in[9];
    const float* dWhh0 = (const float*)d_in[10];
    const float* dbih0 = (const float*)d_in[11];
    const float* dbhh0 = (const float*)d_in[12];
    const float* dWih1 = (const float*)d_in[13];
    const float* dWhh1 = (const float*)d_in[14];
    const float* dbih1 = (const float*)d_in[15];
    const float* dbhh1 = (const float*)d_in[16];
    const float* fcW   = (const float*)d_in[17];
    const float* fcb   = (const float*)d_in[18];
    float* out = (float*)d_out;

    cudaFuncSetAttribute(seq2seq_kernel,
                         cudaFuncAttributeMaxDynamicSharedMemorySize, SMEM_BYTES);

    xg0_kernel<<<B_TOT / 32, 256>>>(x, eWih0, ebih0, ebhh0);
    seq2seq_kernel<<<B_TOT / 32, 256, SMEM_BYTES>>>(
        eWhh0, eWih1, eWhh1, ebih1, ebhh1,
        dWih0, dWhh0, dbih0, dbhh0, dWih1, dWhh1, dbih1, dbhh1,
        fcW, fcb, out);
}

// round 13
// speedup vs baseline: 3.0669x; 1.0362x over previous
#include <cuda_runtime.h>

#define B_TOT 4096
#define T_ENC 168
#define T_DEC 24
#define NF    32
#define NT    8
#define HID   64
#define NG    256   // 4*HID

// Phase-1 scratch: XG0[b][t][g] = x[b,t,:] @ Wih0^T + bih0 + bhh0  (704 MB)
__device__ float g_xg0[(size_t)B_TOT * T_ENC * NG];

typedef unsigned int u32;

// ---------------------------------------------------------------------------
// activations + tf32 convert
// ---------------------------------------------------------------------------
__device__ __forceinline__ float ftanh(float x) {      // MUFU.TANH
    float y;
    asm("tanh.approx.f32 %0, %1;" : "=f"(y) : "f"(x));
    return y;
}
__device__ __forceinline__ float fsig(float x) {       // 1 MUFU + 1 FMA
    return fmaf(ftanh(0.5f * x), 0.5f, 0.5f);
}
__device__ __forceinline__ u32 f2tf(float f) {         // fp32 -> tf32 bits
    u32 r;
    asm("cvt.rna.tf32.f32 %0, %1;" : "=r"(r) : "f"(f));
    return r;
}

// ---------------------------------------------------------------------------
// m16n8k8 tf32 mma (validated R12): A={a0,a1}=chunk kc rows g/g+8, {a2,a3}=kc+1
// ---------------------------------------------------------------------------
__device__ __forceinline__ void mma_k8(float* d, uint4 a, u32 b0, u32 b1) {
    asm volatile(
        "mma.sync.aligned.m16n8k8.row.col.f32.tf32.tf32.f32 "
        "{%0,%1,%2,%3}, {%4,%5,%6,%7}, {%8,%9}, {%0,%1,%2,%3};"
        : "+f"(d[0]), "+f"(d[1]), "+f"(d[2]), "+f"(d[3])
        : "r"(a.x), "r"(a.y), "r"(a.z), "r"(a.w), "r"(b0), "r"(b1));
}

// B-fragment scatter index for W[n][k] (k4-chunk layout, R11-validated):
// kcblk = k/4, k4 = k%4. Per kcblk: [wq(8)][lane(32)][blk(4)] = 1024 u32.
__device__ __forceinline__ int wfidx4(int kcblk, int k4, int n) {
    int blk = n >> 6, wq = (n >> 3) & 7, gq = n & 7;
    int lane = (gq << 2) | k4;
    return ((kcblk * 8 + wq) * 32 + lane) * 4 + blk;
}

// ---------------------------------------------------------------------------
// A-fragment REPACKED layout (new): [kcp][mt(2)][lane(32)][4]
//   word = (kc&1)*2 + rh, so one uint4 = {a0,a1,a2,a3} for a k8 MMA.
//   8 kcp * 256 = 2048 u32 per 64-k buffer (same size as before).
// ---------------------------------------------------------------------------
__device__ __forceinline__ void gemm_mma(
    float acc[2][4][4], const u32* __restrict__ hf,
    const u32* __restrict__ wf, int nkcp, int lane, int w)
{
#pragma unroll
    for (int kcp = 0; kcp < nkcp; kcp++) {
        uint4 A0 = *(const uint4*)(hf + kcp * 256 + lane * 4);
        uint4 A1 = *(const uint4*)(hf + kcp * 256 + 128 + lane * 4);
        uint4 Bx = *(const uint4*)(wf + (kcp * 16 + w) * 128 + lane * 4);
        uint4 By = *(const uint4*)(wf + (kcp * 16 + 8 + w) * 128 + lane * 4);
        mma_k8(acc[0][0], A0, Bx.x, By.x);
        mma_k8(acc[0][1], A0, Bx.y, By.y);
        mma_k8(acc[0][2], A0, Bx.z, By.z);
        mma_k8(acc[0][3], A0, Bx.w, By.w);
        mma_k8(acc[1][0], A1, Bx.x, By.x);
        mma_k8(acc[1][1], A1, Bx.y, By.y);
        mma_k8(acc[1][2], A1, Bx.z, By.z);
        mma_k8(acc[1][3], A1, Bx.w, By.w);
    }
}

// Fused dual GEMM: one set of A loads feeds acc1 (wf1) AND acc0 (wf0).
__device__ __forceinline__ void gemm_dual(
    float acc1[2][4][4], float acc0[2][4][4], const u32* __restrict__ hf,
    const u32* __restrict__ wf1, const u32* __restrict__ wf0, int lane, int w)
{
#pragma unroll 4
    for (int kcp = 0; kcp < 8; kcp++) {
        uint4 A0 = *(const uint4*)(hf + kcp * 256 + lane * 4);
        uint4 A1 = *(const uint4*)(hf + kcp * 256 + 128 + lane * 4);
        uint4 B1x = *(const uint4*)(wf1 + (kcp * 16 + w) * 128 + lane * 4);
        uint4 B1y = *(const uint4*)(wf1 + (kcp * 16 + 8 + w) * 128 + lane * 4);
        uint4 B0x = *(const uint4*)(wf0 + (kcp * 16 + w) * 128 + lane * 4);
        uint4 B0y = *(const uint4*)(wf0 + (kcp * 16 + 8 + w) * 128 + lane * 4);
        mma_k8(acc1[0][0], A0, B1x.x, B1y.x);
        mma_k8(acc1[0][1], A0, B1x.y, B1y.y);
        mma_k8(acc1[0][2], A0, B1x.z, B1y.z);
        mma_k8(acc1[0][3], A0, B1x.w, B1y.w);
        mma_k8(acc0[0][0], A0, B0x.x, B0y.x);
        mma_k8(acc0[0][1], A0, B0x.y, B0y.y);
        mma_k8(acc0[0][2], A0, B0x.z, B0y.z);
        mma_k8(acc0[0][3], A0, B0x.w, B0y.w);
        mma_k8(acc1[1][0], A1, B1x.x, B1y.x);
        mma_k8(acc1[1][1], A1, B1x.y, B1y.y);
        mma_k8(acc1[1][2], A1, B1x.z, B1y.z);
        mma_k8(acc1[1][3], A1, B1x.w, B1y.w);
        mma_k8(acc0[1][0], A1, B0x.x, B0y.x);
        mma_k8(acc0[1][1], A1, B0x.y, B0y.y);
        mma_k8(acc0[1][2], A1, B0x.z, B0y.z);
        mma_k8(acc0[1][3], A1, B0x.w, B0y.w);
    }
}

// PyTorch gate order: blk0=i, blk1=f, blk2=g, blk3=o.
__device__ __forceinline__ void cell_mma(
    const float acc[2][4][4], float c[2][4], float hn[2][4])
{
#pragma unroll
    for (int mt = 0; mt < 2; mt++)
#pragma unroll
        for (int d = 0; d < 4; d++) {
            float ig = fsig(acc[mt][0][d]);
            float fg = fsig(acc[mt][1][d]);
            float gg = ftanh(acc[mt][2][d]);
            float og = fsig(acc[mt][3][d]);
            float cn = fmaf(fg, c[mt][d], ig * gg);
            c[mt][d] = cn;
            hn[mt][d] = og * ftanh(cn);
        }
}

// Scatter hn into REPACKED A-fragment layout. Value (row16 = rh*8+g,
// j = w*8+2tl+cc): kcp = w, word = (jj>>2)*2 + rh, lane2 = (g<<2)|(jj&3).
__device__ __forceinline__ void hstore_frag(
    const float hn[2][4], u32* __restrict__ dst, int lane, int w)
{
    int g = lane >> 2, tl = lane & 3;
#pragma unroll
    for (int mt = 0; mt < 2; mt++)
#pragma unroll
        for (int d = 0; d < 4; d++) {
            int rh = d >> 1, cc = d & 1;
            int jj = 2 * tl + cc;
            int lane2 = (g << 2) | (jj & 3);
            dst[w * 256 + mt * 128 + lane2 * 4 + (jj >> 2) * 2 + rh] =
                f2tf(hn[mt][d]);
        }
}

// ---------------------------------------------------------------------------
// Phase 1: XG0 via tf32 MMA (R12-proven, repacked A). grid=128, 256 threads.
// ---------------------------------------------------------------------------
__global__ void __launch_bounds__(256) xg0_kernel(
    const float* __restrict__ x, const float* __restrict__ Wih0,
    const float* __restrict__ bih0, const float* __restrict__ bhh0)
{
    __shared__ u32 wfr[8 * 1024];       // Wih0 B-frag, 32 KB
    __shared__ u32 xfr[2][4 * 256];     // x A-frag (4 kcp), double-buffered

    const int tid = threadIdx.x;
    const int b0 = blockIdx.x * 32;
    const int w = tid >> 5, lane = tid & 31;
    const int g = lane >> 2, tl = lane & 3;
    const int colb = w * 8 + 2 * tl;

    for (int idx = tid; idx < NG * NF; idx += 256) {
        int n = idx >> 5, k = idx & 31;
        wfr[wfidx4(k >> 2, k & 3, n)] = f2tf(Wih0[idx]);
    }
    float2 bv[4];
#pragma unroll
    for (int blk = 0; blk < 4; blk++) {
        int cg = blk * 64 + colb;
        bv[blk] = make_float2(bih0[cg] + bhh0[cg], bih0[cg + 1] + bhh0[cg + 1]);
    }

    // x staging: thread owns row xr = tid>>3, k4-chunk kc = tid&7
    const int xr = tid >> 3;
    const int kc = tid & 7;
    const int xmt = xr >> 4, xrr = xr & 15;
    const int xrh = xrr >> 3, xg8 = xrr & 7;
    const u32 xbase = (kc >> 1) * 256 + xmt * 128;
    const u32 xoff = (kc & 1) * 2 + xrh;

    float4 xv = *(const float4*)(x + ((size_t)(b0 + xr) * T_ENC + 0) * NF + kc * 4);
    __syncthreads();                    // wfr ready

    for (int t = 0; t < T_ENC; t++) {
        u32* xf = xfr[t & 1];
        xf[xbase + ((xg8 << 2) | 0) * 4 + xoff] = f2tf(xv.x);
        xf[xbase + ((xg8 << 2) | 1) * 4 + xoff] = f2tf(xv.y);
        xf[xbase + ((xg8 << 2) | 2) * 4 + xoff] = f2tf(xv.z);
        xf[xbase + ((xg8 << 2) | 3) * 4 + xoff] = f2tf(xv.w);
        if (t + 1 < T_ENC)
            xv = *(const float4*)(x + ((size_t)(b0 + xr) * T_ENC + t + 1) * NF + kc * 4);
        __syncthreads();                // xf ready (double-buffered)

        float acc[2][4][4];
#pragma unroll
        for (int mt = 0; mt < 2; mt++)
#pragma unroll
            for (int blk = 0; blk < 4; blk++) {
                acc[mt][blk][0] = bv[blk].x; acc[mt][blk][1] = bv[blk].y;
                acc[mt][blk][2] = bv[blk].x; acc[mt][blk][3] = bv[blk].y;
            }
        gemm_mma(acc, xf, wfr, 4, lane, w);

#pragma unroll
        for (int mt = 0; mt < 2; mt++)
#pragma unroll
            for (int rh = 0; rh < 2; rh++) {
                float* dst = g_xg0 +
                    ((size_t)(b0 + mt * 16 + rh * 8 + g) * T_ENC + t) * NG + colb;
#pragma unroll
                for (int blk = 0; blk < 4; blk++)
                    *(float2*)(dst + blk * 64) =
                        make_float2(acc[mt][blk][rh * 2], acc[mt][blk][rh * 2 + 1]);
            }
    }
}

// ---------------------------------------------------------------------------
// Phase 2 smem (floats).
// w0: 18 kcblk (enc: kcblk 0..15 = eWhh0; kcblk 16..17 = h1B overlay (enc-only)
//     dec: Wih0 = kcblk 0..1, Whh0 = kcblk 2..17)
// w1: 32 kcblk (Wih1 = 0..15, Whh1 = 16..31)
// ---------------------------------------------------------------------------
#define SM_W0    0                      // 18432
#define SM_W1    (SM_W0 + 18 * 1024)    // 32768
#define SM_HF0A  (SM_W1 + 32 * 1024)    // 2048
#define SM_HF0B  (SM_HF0A + 2048)       // 2048 (decoder: h1plain overlay)
#define SM_HF1A  (SM_HF0B + 2048)       // 2048
#define SM_DINA  (SM_HF1A + 2048)       // 256
#define SM_TOTAL (SM_DINA + 256)        // 57600 fl = 230400 B
#define SMEM_BYTES (SM_TOTAL * 4)

__global__ void __launch_bounds__(256, 1) seq2seq_kernel(
    const float* __restrict__ eWhh0,
    const float* __restrict__ eWih1, const float* __restrict__ eWhh1,
    const float* __restrict__ ebih1, const float* __restrict__ ebhh1,
    const float* __restrict__ dWih0, const float* __restrict__ dWhh0,
    const float* __restrict__ dbih0, const float* __restrict__ dbhh0,
    const float* __restrict__ dWih1, const float* __restrict__ dWhh1,
    const float* __restrict__ dbih1, const float* __restrict__ dbhh1,
    const float* __restrict__ fcW, const float* __restrict__ fcBias,
    float* __restrict__ out)
{
    extern __shared__ float sm[];
    u32* w0u  = (u32*)(sm + SM_W0);
    u32* w1u  = (u32*)(sm + SM_W1);
    u32* hF0A = (u32*)(sm + SM_HF0A);
    u32* hF0B = (u32*)(sm + SM_HF0B);
    u32* hF1A = (u32*)(sm + SM_HF1A);
    u32* h1Bp = w0u + 16 * 1024;        // encoder-only h1 buffer B
    u32* dinA = (u32*)(sm + SM_DINA);
    float* h1plain = sm + SM_HF0B;      // decoder-only overlay of hF0B

    const int tid = threadIdx.x;
    const int b0 = blockIdx.x * 32;
    const int w = tid >> 5, lane = tid & 31;
    const int g = lane >> 2, tl = lane & 3;
    const int colb = w * 8 + 2 * tl;

    // ---- biases into registers (enc L1, dec L1, dec L0 — all distinct) ----
    float2 b1v[4], d1v[4], b0v[4];
#pragma unroll
    for (int blk = 0; blk < 4; blk++) {
        int cg = blk * 64 + colb;
        b1v[blk] = make_float2(ebih1[cg] + ebhh1[cg], ebih1[cg + 1] + ebhh1[cg + 1]);
        d1v[blk] = make_float2(dbih1[cg] + dbhh1[cg], dbih1[cg + 1] + dbhh1[cg + 1]);
        b0v[blk] = make_float2(dbih0[cg] + dbhh0[cg], dbih0[cg + 1] + dbhh0[cg + 1]);
    }
    float fcbr = fcBias[tid & 7];

    // ---- encoder weight fill (B-frag layout, tf32) ----
    for (int idx = tid; idx < HID * NG; idx += 256) {
        int k = idx >> 8, n = idx & 255;
        w0u[wfidx4(k >> 2, k & 3, n)]        = f2tf(eWhh0[n * HID + k]);
        w1u[wfidx4(k >> 2, k & 3, n)]        = f2tf(eWih1[n * HID + k]);
        w1u[wfidx4(16 + (k >> 2), k & 3, n)] = f2tf(eWhh1[n * HID + k]);
    }
    for (int idx = tid; idx < 2048; idx += 256) {
        hF0A[idx] = 0u; hF0B[idx] = 0u; hF1A[idx] = 0u; h1Bp[idx] = 0u;
    }
    __syncthreads();

    float c0[2][4] = {}, c1[2][4] = {};
    float acc0[2][4][4], acc1[2][4][4], hn[2][4];
    float2 xgv[2][2][4];

    // ================= encoder: fused L1(i)+L0(i+1), ONE barrier/iter =======
    // Prologue: h0(0) = cell(xg(0)) -> hF0A   (h0/c0 init are zero)
    {
#pragma unroll
        for (int mt = 0; mt < 2; mt++)
#pragma unroll
            for (int rh = 0; rh < 2; rh++) {
                const float* srow = g_xg0 +
                    ((size_t)(b0 + mt * 16 + rh * 8 + g) * T_ENC + 0) * NG + colb;
#pragma unroll
                for (int blk = 0; blk < 4; blk++) {
                    float2 v = *(const float2*)(srow + blk * 64);
                    acc0[mt][blk][rh * 2] = v.x;
                    acc0[mt][blk][rh * 2 + 1] = v.y;
                }
            }
        cell_mma(acc0, c0, hn);
        hstore_frag(hn, hF0A, lane, w);
        __syncthreads();
    }

    // Iter i computes h1(i) and h0(i+1), i = 0..T_ENC-2
    for (int i = 0; i < T_ENC - 1; i++) {
        u32* h0cur = (i & 1) ? hF0B : hF0A;
        u32* h0nxt = (i & 1) ? hF0A : hF0B;
        u32* h1rd  = (i & 1) ? hF1A : h1Bp;    // h1(i-1); h1(-1)=0 in h1Bp
        u32* h1wr  = (i & 1) ? h1Bp : hF1A;    // h1(i)

        // acc1 = b1 (L1 gates), acc0 = 0 (L0(i+1) recurrent part)
#pragma unroll
        for (int mt = 0; mt < 2; mt++)
#pragma unroll
            for (int blk = 0; blk < 4; blk++) {
                acc1[mt][blk][0] = b1v[blk].x; acc1[mt][blk][1] = b1v[blk].y;
                acc1[mt][blk][2] = b1v[blk].x; acc1[mt][blk][3] = b1v[blk].y;
                acc0[mt][blk][0] = 0.f; acc0[mt][blk][1] = 0.f;
                acc0[mt][blk][2] = 0.f; acc0[mt][blk][3] = 0.f;
            }

        // h0(i) feeds BOTH Wih1 (acc1) and Whh0 (acc0) — shared A loads
        gemm_dual(acc1, acc0, h0cur, w1u, w0u, lane, w);

        // prefetch xg(i+1); covered by the h1 GEMM below
#pragma unroll
        for (int mt = 0; mt < 2; mt++)
#pragma unroll
            for (int rh = 0; rh < 2; rh++) {
                const float* srow = g_xg0 +
                    ((size_t)(b0 + mt * 16 + rh * 8 + g) * T_ENC + (i + 1)) * NG + colb;
#pragma unroll
                for (int blk = 0; blk < 4; blk++)
                    xgv[mt][rh][blk] = *(const float2*)(srow + blk * 64);
            }

        // acc1 += Whh1 x h1(i-1)
        gemm_mma(acc1, h1rd, w1u + 16 * 1024, 8, lane, w);

        cell_mma(acc1, c1, hn);
        hstore_frag(hn, h1wr, lane, w);        // WAR-safe: alternate buffer

#pragma unroll
        for (int mt = 0; mt < 2; mt++)
#pragma unroll
            for (int blk = 0; blk < 4; blk++) {
                acc0[mt][blk][0] += xgv[mt][0][blk].x;
                acc0[mt][blk][1] += xgv[mt][0][blk].y;
                acc0[mt][blk][2] += xgv[mt][1][blk].x;
                acc0[mt][blk][3] += xgv[mt][1][blk].y;
            }
        cell_mma(acc0, c0, hn);
        hstore_frag(hn, h0nxt, lane, w);       // WAR-safe: alternate buffer

        __syncthreads();                        // publish h1(i), h0(i+1)
    }

    // Epilogue: h1(167). h0(167) in hF0B (i=166 even -> h0nxt=B);
    // h1(166) in hF1A (i=166 even -> h1wr=hF1A).
    {
#pragma unroll
        for (int mt = 0; mt < 2; mt++)
#pragma unroll
            for (int blk = 0; blk < 4; blk++) {
                acc1[mt][blk][0] = b1v[blk].x; acc1[mt][blk][1] = b1v[blk].y;
                acc1[mt][blk][2] = b1v[blk].x; acc1[mt][blk][3] = b1v[blk].y;
            }
        gemm_mma(acc1, hF0B, w1u, 8, lane, w);
        gemm_mma(acc1, hF1A, w1u + 16 * 1024, 8, lane, w);
        cell_mma(acc1, c1, hn);
        __syncthreads();                        // all reads of hF1A done
        hstore_frag(hn, hF1A, lane, w);        // h1(167) -> A
        // h0(167): copy B -> A (decoder reads hF0A)
        for (int idx = tid; idx < 2048; idx += 256) hF0A[idx] = hF0B[idx];
        __syncthreads();
    }

    // ---- decoder weight fill (overwrites h1Bp region and w0) ----
    for (int idx = tid; idx < NT * NG; idx += 256) {      // Wih0: kcblk 0..1
        int k = idx >> 8, n = idx & 255;
        w0u[wfidx4(k >> 2, k & 3, n)] = f2tf(dWih0[n * NT + k]);
    }
    for (int idx = tid; idx < HID * NG; idx += 256) {
        int k = idx >> 8, n = idx & 255;
        w0u[wfidx4(2 + (k >> 2), k & 3, n)]  = f2tf(dWhh0[n * HID + k]);
        w1u[wfidx4(k >> 2, k & 3, n)]        = f2tf(dWih1[n * HID + k]);
        w1u[wfidx4(16 + (k >> 2), k & 3, n)] = f2tf(dWhh1[n * HID + k]);
    }
    for (int idx = tid; idx < 256; idx += 256) dinA[idx] = 0u;
    __syncthreads();

    // ================= decoder =================
    for (int s = 0; s < T_DEC; s++) {
        // L0: b0 + Wih0 x din (1 kcp) + Whh0 x h0 (8 kcp)
#pragma unroll
        for (int mt = 0; mt < 2; mt++)
#pragma unroll
            for (int blk = 0; blk < 4; blk++) {
                acc0[mt][blk][0] = b0v[blk].x; acc0[mt][blk][1] = b0v[blk].y;
                acc0[mt][blk][2] = b0v[blk].x; acc0[mt][blk][3] = b0v[blk].y;
            }
        gemm_mma(acc0, dinA, w0u, 1, lane, w);
        gemm_mma(acc0, hF0A, w0u + 2 * 1024, 8, lane, w);
        cell_mma(acc0, c0, hn);
        __syncthreads();
        hstore_frag(hn, hF0A, lane, w);
        __syncthreads();

        // L1: d1 + Wih1 x h0 + Whh1 x h1
#pragma unroll
        for (int mt = 0; mt < 2; mt++)
#pragma unroll
            for (int blk = 0; blk < 4; blk++) {
                acc1[mt][blk][0] = d1v[blk].x; acc1[mt][blk][1] = d1v[blk].y;
                acc1[mt][blk][2] = d1v[blk].x; acc1[mt][blk][3] = d1v[blk].y;
            }
        gemm_mma(acc1, hF0A, w1u, 8, lane, w);
        gemm_mma(acc1, hF1A, w1u + 16 * 1024, 8, lane, w);
        cell_mma(acc1, c1, hn);
        __syncthreads();
        hstore_frag(hn, hF1A, lane, w);
        // plain fp32 h1 copy for the FC
#pragma unroll
        for (int mt = 0; mt < 2; mt++)
#pragma unroll
            for (int d = 0; d < 4; d++) {
                int r = mt * 16 + (d >> 1) * 8 + g;
                int j = colb + (d & 1);
                h1plain[j * 32 + r] = hn[mt][d];
            }
        __syncthreads();                 // h1plain visible to FC

        // FC: one (row, out) per thread
        {
            int r = tid >> 3, o = tid & 7;
            float a = fcbr;
#pragma unroll 8
            for (int j = 0; j < HID; j++)
                a = fmaf(h1plain[j * 32 + r], fcW[o * HID + j], a);
            out[((size_t)(b0 + r) * T_DEC + s) * NT + o] = a;
            // scatter into din A-frag (repacked): kcp=0, word=(o>>2)*2+rh
            int lane2 = ((r & 7) << 2) | (o & 3);
            dinA[(r >> 4) * 128 + lane2 * 4 + (o >> 2) * 2 + ((r >> 3) & 1)] = f2tf(a);
        }
        __syncthreads();                 // dinA visible to next L0
    }
}

// ---------------------------------------------------------------------------
extern "C" void kernel_launch(void* const* d_in, const int* in_sizes, int n_in,
                              void* d_out, int out_size)
{
    const float* x     = (const float*)d_in[0];
    const float* eWih0 = (const float*)d_in[1];
    const float* eWhh0 = (const float*)d_in[2];
    const float* ebih0 = (const float*)d_in[3];
    const float* ebhh0 = (const float*)d_in[4];
    const float* eWih1 = (const float*)d_in[5];
    const float* eWhh1 = (const float*)d_in[6];
    const float* ebih1 = (const float*)d_in[7];
    const float* ebhh1 = (const float*)d_in[8];
    const float* dWih0 = (const float*)d_in[9];
    const float* dWhh0 = (const float*)d_in[10];
    const float* dbih0 = (const float*)d_in[11];
    const float* dbhh0 = (const float*)d_in[12];
    const float* dWih1 = (const float*)d_in[13];
    const float* dWhh1 = (const float*)d_in[14];
    const float* dbih1 = (const float*)d_in[15];
    const float* dbhh1 = (const float*)d_in[16];
    const float* fcW   = (const float*)d_in[17];
    const float* fcb   = (const float*)d_in[18];
    float* out = (float*)d_out;

    cudaFuncSetAttribute(seq2seq_kernel,
                         cudaFuncAttributeMaxDynamicSharedMemorySize, SMEM_BYTES);

    xg0_kernel<<<B_TOT / 32, 256>>>(x, eWih0, ebih0, ebhh0);
    seq2seq_kernel<<<B_TOT / 32, 256, SMEM_BYTES>>>(
        eWhh0, eWih1, eWhh1, ebih1, ebhh1,
        dWih0, dWhh0, dbih0, dbhh0, dWih1, dWhh1, dbih1, dbhh1,
        fcW, fcb, out);
}

// round 14
// speedup vs baseline: 3.1063x; 1.0128x over previous
#include <cuda_runtime.h>

#define B_TOT 4096
#define T_ENC 168
#define T_DEC 24
#define NF    32
#define NT    8
#define HID   64
#define NG    256   // 4*HID

// Phase-1 scratch: XG0[b][t][g] = x[b,t,:] @ Wih0^T + bih0 + bhh0  (704 MB)
__device__ float g_xg0[(size_t)B_TOT * T_ENC * NG];

typedef unsigned int u32;

// ---------------------------------------------------------------------------
// activations + tf32 convert
// ---------------------------------------------------------------------------
__device__ __forceinline__ float ftanh(float x) {      // MUFU.TANH
    float y;
    asm("tanh.approx.f32 %0, %1;" : "=f"(y) : "f"(x));
    return y;
}
__device__ __forceinline__ float fsig(float x) {       // 1 MUFU + 1 FMA
    return fmaf(ftanh(0.5f * x), 0.5f, 0.5f);
}
__device__ __forceinline__ u32 f2tf(float f) {         // fp32 -> tf32 bits
    u32 r;
    asm("cvt.rna.tf32.f32 %0, %1;" : "=r"(r) : "f"(f));
    return r;
}

// ---------------------------------------------------------------------------
// m16n8k8 tf32 mma (validated R12/R13)
// ---------------------------------------------------------------------------
__device__ __forceinline__ void mma_k8(float* d, uint4 a, u32 b0, u32 b1) {
    asm volatile(
        "mma.sync.aligned.m16n8k8.row.col.f32.tf32.tf32.f32 "
        "{%0,%1,%2,%3}, {%4,%5,%6,%7}, {%8,%9}, {%0,%1,%2,%3};"
        : "+f"(d[0]), "+f"(d[1]), "+f"(d[2]), "+f"(d[3])
        : "r"(a.x), "r"(a.y), "r"(a.z), "r"(a.w), "r"(b0), "r"(b1));
}

// B-fragment scatter index for W[n][k] (R11-validated).
__device__ __forceinline__ int wfidx4(int kcblk, int k4, int n) {
    int blk = n >> 6, wq = (n >> 3) & 7, gq = n & 7;
    int lane = (gq << 2) | k4;
    return ((kcblk * 8 + wq) * 32 + lane) * 4 + blk;
}

// ---------------------------------------------------------------------------
// Half-tile GEMM (one mt per warp): hf_mt = A-frag base already offset by
// mt*128; stride 256 per kcp. acc[blk][4].
// ---------------------------------------------------------------------------
__device__ __forceinline__ void gemm_half(
    float acc[4][4], const u32* __restrict__ hf_mt,
    const u32* __restrict__ wf, int nkcp, int lane, int wq)
{
#pragma unroll
    for (int kcp = 0; kcp < nkcp; kcp++) {
        uint4 A = *(const uint4*)(hf_mt + kcp * 256 + lane * 4);
        uint4 Bx = *(const uint4*)(wf + (kcp * 16 + wq) * 128 + lane * 4);
        uint4 By = *(const uint4*)(wf + (kcp * 16 + 8 + wq) * 128 + lane * 4);
        mma_k8(acc[0], A, Bx.x, By.x);
        mma_k8(acc[1], A, Bx.y, By.y);
        mma_k8(acc[2], A, Bx.z, By.z);
        mma_k8(acc[3], A, Bx.w, By.w);
    }
}

// Fused dual half-GEMM: shared A loads feed acc1 (wf1) and acc0 (wf0).
__device__ __forceinline__ void gemm_dual_half(
    float acc1[4][4], float acc0[4][4], const u32* __restrict__ hf_mt,
    const u32* __restrict__ wf1, const u32* __restrict__ wf0, int lane, int wq)
{
#pragma unroll
    for (int kcp = 0; kcp < 8; kcp++) {
        uint4 A = *(const uint4*)(hf_mt + kcp * 256 + lane * 4);
        uint4 B1x = *(const uint4*)(wf1 + (kcp * 16 + wq) * 128 + lane * 4);
        uint4 B1y = *(const uint4*)(wf1 + (kcp * 16 + 8 + wq) * 128 + lane * 4);
        uint4 B0x = *(const uint4*)(wf0 + (kcp * 16 + wq) * 128 + lane * 4);
        uint4 B0y = *(const uint4*)(wf0 + (kcp * 16 + 8 + wq) * 128 + lane * 4);
        mma_k8(acc1[0], A, B1x.x, B1y.x);
        mma_k8(acc1[1], A, B1x.y, B1y.y);
        mma_k8(acc1[2], A, B1x.z, B1y.z);
        mma_k8(acc1[3], A, B1x.w, B1y.w);
        mma_k8(acc0[0], A, B0x.x, B0y.x);
        mma_k8(acc0[1], A, B0x.y, B0y.y);
        mma_k8(acc0[2], A, B0x.z, B0y.z);
        mma_k8(acc0[3], A, B0x.w, B0y.w);
    }
}

// PyTorch gate order: blk0=i, blk1=f, blk2=g, blk3=o.
__device__ __forceinline__ void cell_half(
    const float acc[4][4], float c[4], float hn[4])
{
#pragma unroll
    for (int d = 0; d < 4; d++) {
        float ig = fsig(acc[0][d]);
        float fg = fsig(acc[1][d]);
        float gg = ftanh(acc[2][d]);
        float og = fsig(acc[3][d]);
        float cn = fmaf(fg, c[d], ig * gg);
        c[d] = cn;
        hn[d] = og * ftanh(cn);
    }
}

// Scatter hn (one mt) into repacked A-fragment layout.
__device__ __forceinline__ void hstore_half(
    const float hn[4], u32* __restrict__ dst, int lane, int wq, int mt)
{
    int g = lane >> 2, tl = lane & 3;
#pragma unroll
    for (int d = 0; d < 4; d++) {
        int rh = d >> 1, cc = d & 1;
        int jj = 2 * tl + cc;
        int lane2 = (g << 2) | (jj & 3);
        dst[wq * 256 + mt * 128 + lane2 * 4 + (jj >> 2) * 2 + rh] = f2tf(hn[d]);
    }
}

// ---------------------------------------------------------------------------
// Phase 1: XG0 via tf32 MMA (R13-proven, unchanged). grid=128, 256 threads.
// ---------------------------------------------------------------------------
__device__ __forceinline__ void gemm_mma_full(
    float acc[2][4][4], const u32* __restrict__ hf,
    const u32* __restrict__ wf, int nkcp, int lane, int w)
{
#pragma unroll
    for (int kcp = 0; kcp < nkcp; kcp++) {
        uint4 A0 = *(const uint4*)(hf + kcp * 256 + lane * 4);
        uint4 A1 = *(const uint4*)(hf + kcp * 256 + 128 + lane * 4);
        uint4 Bx = *(const uint4*)(wf + (kcp * 16 + w) * 128 + lane * 4);
        uint4 By = *(const uint4*)(wf + (kcp * 16 + 8 + w) * 128 + lane * 4);
        mma_k8(acc[0][0], A0, Bx.x, By.x);
        mma_k8(acc[0][1], A0, Bx.y, By.y);
        mma_k8(acc[0][2], A0, Bx.z, By.z);
        mma_k8(acc[0][3], A0, Bx.w, By.w);
        mma_k8(acc[1][0], A1, Bx.x, By.x);
        mma_k8(acc[1][1], A1, Bx.y, By.y);
        mma_k8(acc[1][2], A1, Bx.z, By.z);
        mma_k8(acc[1][3], A1, Bx.w, By.w);
    }
}

__global__ void __launch_bounds__(256) xg0_kernel(
    const float* __restrict__ x, const float* __restrict__ Wih0,
    const float* __restrict__ bih0, const float* __restrict__ bhh0)
{
    __shared__ u32 wfr[8 * 1024];       // Wih0 B-frag, 32 KB
    __shared__ u32 xfr[2][4 * 256];     // x A-frag (4 kcp), double-buffered

    const int tid = threadIdx.x;
    const int b0 = blockIdx.x * 32;
    const int w = tid >> 5, lane = tid & 31;
    const int g = lane >> 2, tl = lane & 3;
    const int colb = w * 8 + 2 * tl;

    for (int idx = tid; idx < NG * NF; idx += 256) {
        int n = idx >> 5, k = idx & 31;
        wfr[wfidx4(k >> 2, k & 3, n)] = f2tf(Wih0[idx]);
    }
    float2 bv[4];
#pragma unroll
    for (int blk = 0; blk < 4; blk++) {
        int cg = blk * 64 + colb;
        bv[blk] = make_float2(bih0[cg] + bhh0[cg], bih0[cg + 1] + bhh0[cg + 1]);
    }

    const int xr = tid >> 3;
    const int kc = tid & 7;
    const int xmt = xr >> 4, xrr = xr & 15;
    const int xrh = xrr >> 3, xg8 = xrr & 7;
    const u32 xbase = (kc >> 1) * 256 + xmt * 128;
    const u32 xoff = (kc & 1) * 2 + xrh;

    float4 xv = *(const float4*)(x + ((size_t)(b0 + xr) * T_ENC + 0) * NF + kc * 4);
    __syncthreads();                    // wfr ready

    for (int t = 0; t < T_ENC; t++) {
        u32* xf = xfr[t & 1];
        xf[xbase + ((xg8 << 2) | 0) * 4 + xoff] = f2tf(xv.x);
        xf[xbase + ((xg8 << 2) | 1) * 4 + xoff] = f2tf(xv.y);
        xf[xbase + ((xg8 << 2) | 2) * 4 + xoff] = f2tf(xv.z);
        xf[xbase + ((xg8 << 2) | 3) * 4 + xoff] = f2tf(xv.w);
        if (t + 1 < T_ENC)
            xv = *(const float4*)(x + ((size_t)(b0 + xr) * T_ENC + t + 1) * NF + kc * 4);
        __syncthreads();                // xf ready (double-buffered)

        float acc[2][4][4];
#pragma unroll
        for (int mt = 0; mt < 2; mt++)
#pragma unroll
            for (int blk = 0; blk < 4; blk++) {
                acc[mt][blk][0] = bv[blk].x; acc[mt][blk][1] = bv[blk].y;
                acc[mt][blk][2] = bv[blk].x; acc[mt][blk][3] = bv[blk].y;
            }
        gemm_mma_full(acc, xf, wfr, 4, lane, w);

#pragma unroll
        for (int mt = 0; mt < 2; mt++)
#pragma unroll
            for (int rh = 0; rh < 2; rh++) {
                float* dst = g_xg0 +
                    ((size_t)(b0 + mt * 16 + rh * 8 + g) * T_ENC + t) * NG + colb;
#pragma unroll
                for (int blk = 0; blk < 4; blk++)
                    *(float2*)(dst + blk * 64) =
                        make_float2(acc[mt][blk][rh * 2], acc[mt][blk][rh * 2 + 1]);
            }
    }
}

// ---------------------------------------------------------------------------
// Phase 2 smem (floats). Same proven layout as R13.
// ---------------------------------------------------------------------------
#define SM_W0    0                      // 18 kcblk
#define SM_W1    (SM_W0 + 18 * 1024)    // 32 kcblk
#define SM_HF0A  (SM_W1 + 32 * 1024)
#define SM_HF0B  (SM_HF0A + 2048)       // decoder: h1plain overlay
#define SM_HF1A  (SM_HF0B + 2048)
#define SM_DINA  (SM_HF1A + 2048)
#define SM_TOTAL (SM_DINA + 256)        // 57600 fl = 230400 B
#define SMEM_BYTES (SM_TOTAL * 4)

__global__ void __launch_bounds__(512, 1) seq2seq_kernel(
    const float* __restrict__ eWhh0,
    const float* __restrict__ eWih1, const float* __restrict__ eWhh1,
    const float* __restrict__ ebih1, const float* __restrict__ ebhh1,
    const float* __restrict__ dWih0, const float* __restrict__ dWhh0,
    const float* __restrict__ dbih0, const float* __restrict__ dbhh0,
    const float* __restrict__ dWih1, const float* __restrict__ dWhh1,
    const float* __restrict__ dbih1, const float* __restrict__ dbhh1,
    const float* __restrict__ fcW, const float* __restrict__ fcBias,
    float* __restrict__ out)
{
    extern __shared__ float sm[];
    u32* w0u  = (u32*)(sm + SM_W0);
    u32* w1u  = (u32*)(sm + SM_W1);
    u32* hF0A = (u32*)(sm + SM_HF0A);
    u32* hF0B = (u32*)(sm + SM_HF0B);
    u32* hF1A = (u32*)(sm + SM_HF1A);
    u32* h1Bp = w0u + 16 * 1024;        // encoder-only h1 buffer B
    u32* dinA = (u32*)(sm + SM_DINA);
    float* h1plain = sm + SM_HF0B;      // decoder-only overlay of hF0B

    const int tid = threadIdx.x;
    const int b0 = blockIdx.x * 32;
    const int w = tid >> 5, lane = tid & 31;
    const int wq = w & 7, mt = w >> 3;   // n-slice, m-half
    const int g = lane >> 2, tl = lane & 3;
    const int colb = wq * 8 + 2 * tl;
    const int mtoff = mt * 128;          // A-frag offset of this warp's m-half

    // ---- biases into registers (per-warp gate columns) ----
    float2 b1v[4], d1v[4], b0v[4];
#pragma unroll
    for (int blk = 0; blk < 4; blk++) {
        int cg = blk * 64 + colb;
        b1v[blk] = make_float2(ebih1[cg] + ebhh1[cg], ebih1[cg + 1] + ebhh1[cg + 1]);
        d1v[blk] = make_float2(dbih1[cg] + dbhh1[cg], dbih1[cg + 1] + dbhh1[cg + 1]);
        b0v[blk] = make_float2(dbih0[cg] + dbhh0[cg], dbih0[cg + 1] + dbhh0[cg + 1]);
    }
    float fcbr = fcBias[tid & 7];

    // ---- encoder weight fill (B-frag layout, tf32) ----
    for (int idx = tid; idx < HID * NG; idx += 512) {
        int k = idx >> 8, n = idx & 255;
        w0u[wfidx4(k >> 2, k & 3, n)]        = f2tf(eWhh0[n * HID + k]);
        w1u[wfidx4(k >> 2, k & 3, n)]        = f2tf(eWih1[n * HID + k]);
        w1u[wfidx4(16 + (k >> 2), k & 3, n)] = f2tf(eWhh1[n * HID + k]);
    }
    for (int idx = tid; idx < 2048; idx += 512) {
        hF0A[idx] = 0u; hF0B[idx] = 0u; hF1A[idx] = 0u; h1Bp[idx] = 0u;
    }
    __syncthreads();

    float c0[4] = {}, c1[4] = {};
    float acc0[4][4], acc1[4][4], hn[4];
    float2 xgv[2][4];

    // ================= encoder: fused L1(i)+L0(i+1), ONE barrier/iter =======
    // Prologue: h0(0) = cell(xg(0)) -> hF0A
    {
#pragma unroll
        for (int rh = 0; rh < 2; rh++) {
            const float* srow = g_xg0 +
                ((size_t)(b0 + mt * 16 + rh * 8 + g) * T_ENC + 0) * NG + colb;
#pragma unroll
            for (int blk = 0; blk < 4; blk++) {
                float2 v = *(const float2*)(srow + blk * 64);
                acc0[blk][rh * 2] = v.x;
                acc0[blk][rh * 2 + 1] = v.y;
            }
        }
        cell_half(acc0, c0, hn);
        hstore_half(hn, hF0A, lane, wq, mt);
        __syncthreads();
    }

    // Iter i computes h1(i) and h0(i+1), i = 0..T_ENC-2
    for (int i = 0; i < T_ENC - 1; i++) {
        u32* h0cur = (i & 1) ? hF0B : hF0A;
        u32* h0nxt = (i & 1) ? hF0A : hF0B;
        u32* h1rd  = (i & 1) ? hF1A : h1Bp;    // h1(i-1); h1(-1)=0 in h1Bp
        u32* h1wr  = (i & 1) ? h1Bp : hF1A;    // h1(i)

#pragma unroll
        for (int blk = 0; blk < 4; blk++) {
            acc1[blk][0] = b1v[blk].x; acc1[blk][1] = b1v[blk].y;
            acc1[blk][2] = b1v[blk].x; acc1[blk][3] = b1v[blk].y;
            acc0[blk][0] = 0.f; acc0[blk][1] = 0.f;
            acc0[blk][2] = 0.f; acc0[blk][3] = 0.f;
        }

        // h0(i) feeds BOTH Wih1 (acc1) and Whh0 (acc0) — shared A loads
        gemm_dual_half(acc1, acc0, h0cur + mtoff, w1u, w0u, lane, wq);

        // prefetch xg(i+1); covered by the h1 GEMM below
#pragma unroll
        for (int rh = 0; rh < 2; rh++) {
            const float* srow = g_xg0 +
                ((size_t)(b0 + mt * 16 + rh * 8 + g) * T_ENC + (i + 1)) * NG + colb;
#pragma unroll
            for (int blk = 0; blk < 4; blk++)
                xgv[rh][blk] = *(const float2*)(srow + blk * 64);
        }

        // acc1 += Whh1 x h1(i-1)
        gemm_half(acc1, h1rd + mtoff, w1u + 16 * 1024, 8, lane, wq);

        cell_half(acc1, c1, hn);
        hstore_half(hn, h1wr, lane, wq, mt);   // WAR-safe: alternate buffer

#pragma unroll
        for (int blk = 0; blk < 4; blk++) {
            acc0[blk][0] += xgv[0][blk].x;
            acc0[blk][1] += xgv[0][blk].y;
            acc0[blk][2] += xgv[1][blk].x;
            acc0[blk][3] += xgv[1][blk].y;
        }
        cell_half(acc0, c0, hn);
        hstore_half(hn, h0nxt, lane, wq, mt);  // WAR-safe: alternate buffer

        __syncthreads();                        // publish h1(i), h0(i+1)
    }

    // Epilogue: h1(167). h0(167) in hF0B; h1(166) in hF1A.
    {
#pragma unroll
        for (int blk = 0; blk < 4; blk++) {
            acc1[blk][0] = b1v[blk].x; acc1[blk][1] = b1v[blk].y;
            acc1[blk][2] = b1v[blk].x; acc1[blk][3] = b1v[blk].y;
        }
        gemm_half(acc1, hF0B + mtoff, w1u, 8, lane, wq);
        gemm_half(acc1, hF1A + mtoff, w1u + 16 * 1024, 8, lane, wq);
        cell_half(acc1, c1, hn);
        __syncthreads();                        // all reads of hF1A done
        hstore_half(hn, hF1A, lane, wq, mt);   // h1(167) -> A
        for (int idx = tid; idx < 2048; idx += 512) hF0A[idx] = hF0B[idx];
        __syncthreads();
    }

    // ---- decoder weight fill (overwrites h1Bp region and w0) ----
    for (int idx = tid; idx < NT * NG; idx += 512) {      // Wih0: kcblk 0..1
        int k = idx >> 8, n = idx & 255;
        w0u[wfidx4(k >> 2, k & 3, n)] = f2tf(dWih0[n * NT + k]);
    }
    for (int idx = tid; idx < HID * NG; idx += 512) {
        int k = idx >> 8, n = idx & 255;
        w0u[wfidx4(2 + (k >> 2), k & 3, n)]  = f2tf(dWhh0[n * HID + k]);
        w1u[wfidx4(k >> 2, k & 3, n)]        = f2tf(dWih1[n * HID + k]);
        w1u[wfidx4(16 + (k >> 2), k & 3, n)] = f2tf(dWhh1[n * HID + k]);
    }
    for (int idx = tid; idx < 256; idx += 512) dinA[idx] = 0u;
    __syncthreads();

    // ================= decoder =================
    for (int s = 0; s < T_DEC; s++) {
        // L0: b0 + Wih0 x din (1 kcp) + Whh0 x h0 (8 kcp)
#pragma unroll
        for (int blk = 0; blk < 4; blk++) {
            acc0[blk][0] = b0v[blk].x; acc0[blk][1] = b0v[blk].y;
            acc0[blk][2] = b0v[blk].x; acc0[blk][3] = b0v[blk].y;
        }
        gemm_half(acc0, dinA + mtoff, w0u, 1, lane, wq);
        gemm_half(acc0, hF0A + mtoff, w0u + 2 * 1024, 8, lane, wq);
        cell_half(acc0, c0, hn);
        __syncthreads();
        hstore_half(hn, hF0A, lane, wq, mt);
        __syncthreads();

        // L1: d1 + Wih1 x h0 + Whh1 x h1
#pragma unroll
        for (int blk = 0; blk < 4; blk++) {
            acc1[blk][0] = d1v[blk].x; acc1[blk][1] = d1v[blk].y;
            acc1[blk][2] = d1v[blk].x; acc1[blk][3] = d1v[blk].y;
        }
        gemm_half(acc1, hF0A + mtoff, w1u, 8, lane, wq);
        gemm_half(acc1, hF1A + mtoff, w1u + 16 * 1024, 8, lane, wq);
        cell_half(acc1, c1, hn);
        __syncthreads();
        hstore_half(hn, hF1A, lane, wq, mt);
        // plain fp32 h1 copy for the FC
#pragma unroll
        for (int d = 0; d < 4; d++) {
            int r = mt * 16 + (d >> 1) * 8 + g;
            int j = colb + (d & 1);
            h1plain[j * 32 + r] = hn[d];
        }
        __syncthreads();                 // h1plain visible to FC

        // FC: threads 0..255, one (row, out) each
        if (tid < 256) {
            int r = tid >> 3, o = tid & 7;
            float a = fcbr;
#pragma unroll 8
            for (int j = 0; j < HID; j++)
                a = fmaf(h1plain[j * 32 + r], fcW[o * HID + j], a);
            out[((size_t)(b0 + r) * T_DEC + s) * NT + o] = a;
            // scatter into din A-frag (repacked): kcp=0
            int lane2 = ((r & 7) << 2) | (o & 3);
            dinA[(r >> 4) * 128 + lane2 * 4 + (o >> 2) * 2 + ((r >> 3) & 1)] = f2tf(a);
        }
        __syncthreads();                 // dinA visible to next L0
    }
}

// ---------------------------------------------------------------------------
extern "C" void kernel_launch(void* const* d_in, const int* in_sizes, int n_in,
                              void* d_out, int out_size)
{
    const float* x     = (const float*)d_in[0];
    const float* eWih0 = (const float*)d_in[1];
    const float* eWhh0 = (const float*)d_in[2];
    const float* ebih0 = (const float*)d_in[3];
    const float* ebhh0 = (const float*)d_in[4];
    const float* eWih1 = (const float*)d_in[5];
    const float* eWhh1 = (const float*)d_in[6];
    const float* ebih1 = (const float*)d_in[7];
    const float* ebhh1 = (const float*)d_in[8];
    const float* dWih0 = (const float*)d_in[9];
    const float* dWhh0 = (const float*)d_in[10];
    const float* dbih0 = (const float*)d_in[11];
    const float* dbhh0 = (const float*)d_in[12];
    const float* dWih1 = (const float*)d_in[13];
    const float* dWhh1 = (const float*)d_in[14];
    const float* dbih1 = (const float*)d_in[15];
    const float* dbhh1 = (const float*)d_in[16];
    const float* fcW   = (const float*)d_in[17];
    const float* fcb   = (const float*)d_in[18];
    float* out = (float*)d_out;

    cudaFuncSetAttribute(seq2seq_kernel,
                         cudaFuncAttributeMaxDynamicSharedMemorySize, SMEM_BYTES);

    xg0_kernel<<<B_TOT / 32, 256>>>(x, eWih0, ebih0, ebhh0);
    seq2seq_kernel<<<B_TOT / 32, 512, SMEM_BYTES>>>(
        eWhh0, eWih1, eWhh1, ebih1, ebhh1,
        dWih0, dWhh0, dbih0, dbhh0, dWih1, dWhh1, dbih1, dbhh1,
        fcW, fcb, out);
}

// round 17
// speedup vs baseline: 3.8971x; 1.2546x over previous
#include <cuda_runtime.h>
#include <cuda_bf16.h>

#define B_TOT 4096
#define T_ENC 168
#define T_DEC 24
#define NF    32
#define NT    8
#define HID   64
#define NG    256   // 4*HID

// Phase-1 scratch: XG0[b][t][g] = x[b,t,:] @ Wih0^T + bih0 + bhh0  (704 MB)
__device__ float g_xg0[(size_t)B_TOT * T_ENC * NG];

typedef unsigned int u32;

// ---------------------------------------------------------------------------
// activations + converts
// ---------------------------------------------------------------------------
__device__ __forceinline__ float ftanh(float x) {      // MUFU.TANH
    float y;
    asm("tanh.approx.f32 %0, %1;" : "=f"(y) : "f"(x));
    return y;
}
__device__ __forceinline__ float fsig(float x) {       // 1 MUFU + 1 FMA
    return fmaf(ftanh(0.5f * x), 0.5f, 0.5f);
}
__device__ __forceinline__ u32 f2tf(float f) {         // fp32 -> tf32 bits
    u32 r;
    asm("cvt.rna.tf32.f32 %0, %1;" : "=r"(r) : "f"(f));
    return r;
}
__device__ __forceinline__ u32 pack_bf2(float lo, float hi) {  // {hi,lo} bf16x2
    u32 r;
    asm("cvt.rn.bf16x2.f32 %0, %1, %2;" : "=r"(r) : "f"(hi), "f"(lo));
    return r;
}

// ---------------------------------------------------------------------------
// bf16 m16n8k16 mma (fp32 accum). Standard fp16-family fragments:
//   A: a0=(g, k=2t,2t+1) a1=(g+8, same) a2=(g, k=8+2t..) a3=(g+8, ..)
//   B: b0=(k=2t,2t+1, col g)  b1=(k=8+2t.., col g)   (lo bf16 = even k)
//   C: c0=(g,2t) c1=(g,2t+1) c2=(g+8,2t) c3=(g+8,2t+1)
// ---------------------------------------------------------------------------
__device__ __forceinline__ void mma_bf(float* d, uint4 a, u32 b0, u32 b1) {
    asm volatile(
        "mma.sync.aligned.m16n8k16.row.col.f32.bf16.bf16.f32 "
        "{%0,%1,%2,%3}, {%4,%5,%6,%7}, {%8,%9}, {%0,%1,%2,%3};"
        : "+f"(d[0]), "+f"(d[1]), "+f"(d[2]), "+f"(d[3])
        : "r"(a.x), "r"(a.y), "r"(a.z), "r"(a.w), "r"(b0), "r"(b1));
}

// bf16 B-frag scatter: W[n][k] -> u16 index.
// Per kb (k16 block): [wq(8)][half(2)][lane(32)][blk(4)] u32 = 2048 u32.
__device__ __forceinline__ int wbidx16(int k, int n) {
    int kb = k >> 4, kr = k & 15;
    int half = kr >> 3, tig = (kr & 7) >> 1, e = k & 1;
    int blk = n >> 6, wq = (n >> 3) & 7, gq = n & 7;
    int lane = (gq << 2) | tig;
    return ((((kb * 8 + wq) * 2 + half) * 128) + lane * 4 + blk) * 2 + e;
}

// bf16 A-frag layout per 64-k buffer: [kb(4)][mt(2)][lane(32)][word(4)] u32,
// word = half*2 + rh, u32 = {even k lo, odd k hi}. 1024 u32 per buffer.
__device__ __forceinline__ void gemm_half(
    float acc[4][4], const u32* __restrict__ hf_mt,
    const u32* __restrict__ wf, int nkb, int lane, int wq)
{
#pragma unroll
    for (int kb = 0; kb < nkb; kb++) {
        uint4 A  = *(const uint4*)(hf_mt + kb * 256 + lane * 4);
        uint4 Bx = *(const uint4*)(wf + ((kb * 8 + wq) * 2 + 0) * 128 + lane * 4);
        uint4 By = *(const uint4*)(wf + ((kb * 8 + wq) * 2 + 1) * 128 + lane * 4);
        mma_bf(acc[0], A, Bx.x, By.x);
        mma_bf(acc[1], A, Bx.y, By.y);
        mma_bf(acc[2], A, Bx.z, By.z);
        mma_bf(acc[3], A, Bx.w, By.w);
    }
}

// Fused dual half-GEMM: shared A loads feed acc1 (wf1) and acc0 (wf0).
__device__ __forceinline__ void gemm_dual_half(
    float acc1[4][4], float acc0[4][4], const u32* __restrict__ hf_mt,
    const u32* __restrict__ wf1, const u32* __restrict__ wf0, int lane, int wq)
{
#pragma unroll
    for (int kb = 0; kb < 4; kb++) {
        uint4 A   = *(const uint4*)(hf_mt + kb * 256 + lane * 4);
        uint4 B1x = *(const uint4*)(wf1 + ((kb * 8 + wq) * 2 + 0) * 128 + lane * 4);
        uint4 B1y = *(const uint4*)(wf1 + ((kb * 8 + wq) * 2 + 1) * 128 + lane * 4);
        uint4 B0x = *(const uint4*)(wf0 + ((kb * 8 + wq) * 2 + 0) * 128 + lane * 4);
        uint4 B0y = *(const uint4*)(wf0 + ((kb * 8 + wq) * 2 + 1) * 128 + lane * 4);
        mma_bf(acc1[0], A, B1x.x, B1y.x);
        mma_bf(acc1[1], A, B1x.y, B1y.y);
        mma_bf(acc1[2], A, B1x.z, B1y.z);
        mma_bf(acc1[3], A, B1x.w, B1y.w);
        mma_bf(acc0[0], A, B0x.x, B0y.x);
        mma_bf(acc0[1], A, B0x.y, B0y.y);
        mma_bf(acc0[2], A, B0x.z, B0y.z);
        mma_bf(acc0[3], A, B0x.w, B0y.w);
    }
}

// PyTorch gate order: blk0=i, blk1=f, blk2=g, blk3=o.  d = rh*2 + cc.
__device__ __forceinline__ void cell_half(
    const float acc[4][4], float c[4], float hn[4])
{
#pragma unroll
    for (int d = 0; d < 4; d++) {
        float ig = fsig(acc[0][d]);
        float fg = fsig(acc[1][d]);
        float gg = ftanh(acc[2][d]);
        float og = fsig(acc[3][d]);
        float cn = fmaf(fg, c[d], ig * gg);
        c[d] = cn;
        hn[d] = og * ftanh(cn);
    }
}

// Scatter hn into bf16 A-frag. Thread value (row=mt*16+rh*8+g, j=wq*8+2tl+cc):
// kb = wq>>1, half = wq&1, tig = tl, e = cc, lane2 = lane.
__device__ __forceinline__ void hstore_half(
    const float hn[4], u32* __restrict__ dst, int lane, int wq, int mt)
{
    int kb = wq >> 1, half = wq & 1;
    u32* p = dst + kb * 256 + mt * 128 + lane * 4 + half * 2;
    p[0] = pack_bf2(hn[0], hn[1]);      // rh=0: cc0 lo, cc1 hi
    p[1] = pack_bf2(hn[2], hn[3]);      // rh=1
}

// ---------------------------------------------------------------------------
// Phase 1: XG0 via tf32 MMA (R13/14-proven, unchanged). grid=128, 256 thr.
// ---------------------------------------------------------------------------
__device__ __forceinline__ void mma_k8(float* d, uint4 a, u32 b0, u32 b1) {
    asm volatile(
        "mma.sync.aligned.m16n8k8.row.col.f32.tf32.tf32.f32 "
        "{%0,%1,%2,%3}, {%4,%5,%6,%7}, {%8,%9}, {%0,%1,%2,%3};"
        : "+f"(d[0]), "+f"(d[1]), "+f"(d[2]), "+f"(d[3])
        : "r"(a.x), "r"(a.y), "r"(a.z), "r"(a.w), "r"(b0), "r"(b1));
}
__device__ __forceinline__ int wfidx4(int kcblk, int k4, int n) {
    int blk = n >> 6, wq = (n >> 3) & 7, gq = n & 7;
    int lane = (gq << 2) | k4;
    return ((kcblk * 8 + wq) * 32 + lane) * 4 + blk;
}
__device__ __forceinline__ void gemm_mma_full(
    float acc[2][4][4], const u32* __restrict__ hf,
    const u32* __restrict__ wf, int nkcp, int lane, int w)
{
#pragma unroll
    for (int kcp = 0; kcp < nkcp; kcp++) {
        uint4 A0 = *(const uint4*)(hf + kcp * 256 + lane * 4);
        uint4 A1 = *(const uint4*)(hf + kcp * 256 + 128 + lane * 4);
        uint4 Bx = *(const uint4*)(wf + (kcp * 16 + w) * 128 + lane * 4);
        uint4 By = *(const uint4*)(wf + (kcp * 16 + 8 + w) * 128 + lane * 4);
        mma_k8(acc[0][0], A0, Bx.x, By.x);
        mma_k8(acc[0][1], A0, Bx.y, By.y);
        mma_k8(acc[0][2], A0, Bx.z, By.z);
        mma_k8(acc[0][3], A0, Bx.w, By.w);
        mma_k8(acc[1][0], A1, Bx.x, By.x);
        mma_k8(acc[1][1], A1, Bx.y, By.y);
        mma_k8(acc[1][2], A1, Bx.z, By.z);
        mma_k8(acc[1][3], A1, Bx.w, By.w);
    }
}

__global__ void __launch_bounds__(256) xg0_kernel(
    const float* __restrict__ x, const float* __restrict__ Wih0,
    const float* __restrict__ bih0, const float* __restrict__ bhh0)
{
    __shared__ u32 wfr[8 * 1024];
    __shared__ u32 xfr[2][4 * 256];

    const int tid = threadIdx.x;
    const int b0 = blockIdx.x * 32;
    const int w = tid >> 5, lane = tid & 31;
    const int g = lane >> 2, tl = lane & 3;
    const int colb = w * 8 + 2 * tl;

    for (int idx = tid; idx < NG * NF; idx += 256) {
        int n = idx >> 5, k = idx & 31;
        wfr[wfidx4(k >> 2, k & 3, n)] = f2tf(Wih0[idx]);
    }
    float2 bv[4];
#pragma unroll
    for (int blk = 0; blk < 4; blk++) {
        int cg = blk * 64 + colb;
        bv[blk] = make_float2(bih0[cg] + bhh0[cg], bih0[cg + 1] + bhh0[cg + 1]);
    }

    const int xr = tid >> 3;
    const int kc = tid & 7;
    const int xmt = xr >> 4, xrr = xr & 15;
    const int xrh = xrr >> 3, xg8 = xrr & 7;
    const u32 xbase = (kc >> 1) * 256 + xmt * 128;
    const u32 xoff = (kc & 1) * 2 + xrh;

    float4 xv = *(const float4*)(x + ((size_t)(b0 + xr) * T_ENC + 0) * NF + kc * 4);
    __syncthreads();

    for (int t = 0; t < T_ENC; t++) {
        u32* xf = xfr[t & 1];
        xf[xbase + ((xg8 << 2) | 0) * 4 + xoff] = f2tf(xv.x);
        xf[xbase + ((xg8 << 2) | 1) * 4 + xoff] = f2tf(xv.y);
        xf[xbase + ((xg8 << 2) | 2) * 4 + xoff] = f2tf(xv.z);
        xf[xbase + ((xg8 << 2) | 3) * 4 + xoff] = f2tf(xv.w);
        if (t + 1 < T_ENC)
            xv = *(const float4*)(x + ((size_t)(b0 + xr) * T_ENC + t + 1) * NF + kc * 4);
        __syncthreads();

        float acc[2][4][4];
#pragma unroll
        for (int mt = 0; mt < 2; mt++)
#pragma unroll
            for (int blk = 0; blk < 4; blk++) {
                acc[mt][blk][0] = bv[blk].x; acc[mt][blk][1] = bv[blk].y;
                acc[mt][blk][2] = bv[blk].x; acc[mt][blk][3] = bv[blk].y;
            }
        gemm_mma_full(acc, xf, wfr, 4, lane, w);

#pragma unroll
        for (int mt = 0; mt < 2; mt++)
#pragma unroll
            for (int rh = 0; rh < 2; rh++) {
                float* dst = g_xg0 +
                    ((size_t)(b0 + mt * 16 + rh * 8 + g) * T_ENC + t) * NG + colb;
#pragma unroll
                for (int blk = 0; blk < 4; blk++)
                    *(float2*)(dst + blk * 64) =
                        make_float2(acc[mt][blk][rh * 2], acc[mt][blk][rh * 2 + 1]);
            }
    }
}

// ---------------------------------------------------------------------------
// Phase 2 smem (u32 units). bf16 weights/h — no overlays needed.
// w0: enc Whh0 = kb 0..3 (8192); dec Wih0 = kb 0 (2048, zero-padded k8..15),
//     dec Whh0 = kb 1..4 (base +2048).
// w1: Wih1 kb 0..3; Whh1 kb 4..7 (base +8192).
// ---------------------------------------------------------------------------
#define SW0   0
#define SW1   (SW0 + 10240)
#define SH0A  (SW1 + 16384)
#define SH0B  (SH0A + 1024)
#define SH1A  (SH0B + 1024)
#define SH1B  (SH1A + 1024)
#define SDIN  (SH1B + 1024)
#define SH1P  (SDIN + 256)      // fp32 h1plain (decoder FC)
#define STOT  (SH1P + 2048)     // 33024 u32 = 132096 B
#define SMEM_BYTES (STOT * 4)

__global__ void __launch_bounds__(512, 1) seq2seq_kernel(
    const float* __restrict__ eWhh0,
    const float* __restrict__ eWih1, const float* __restrict__ eWhh1,
    const float* __restrict__ ebih1, const float* __restrict__ ebhh1,
    const float* __restrict__ dWih0, const float* __restrict__ dWhh0,
    const float* __restrict__ dbih0, const float* __restrict__ dbhh0,
    const float* __restrict__ dWih1, const float* __restrict__ dWhh1,
    const float* __restrict__ dbih1, const float* __restrict__ dbhh1,
    const float* __restrict__ fcW, const float* __restrict__ fcBias,
    float* __restrict__ out)
{
    extern __shared__ u32 smu[];
    u32* w0u  = smu + SW0;
    u32* w1u  = smu + SW1;
    u32* hF0A = smu + SH0A;
    u32* hF0B = smu + SH0B;
    u32* hF1A = smu + SH1A;
    u32* hF1B = smu + SH1B;
    u32* dinA = smu + SDIN;
    float* h1plain = (float*)(smu + SH1P);
    __nv_bfloat16* w0h = (__nv_bfloat16*)w0u;
    __nv_bfloat16* w1h = (__nv_bfloat16*)w1u;

    const int tid = threadIdx.x;
    const int b0 = blockIdx.x * 32;
    const int w = tid >> 5, lane = tid & 31;
    const int wq = w & 7, mt = w >> 3;   // n-slice, m-half
    const int g = lane >> 2, tl = lane & 3;
    const int colb = wq * 8 + 2 * tl;
    const int mtoff = mt * 128;

    // ---- biases into registers ----
    float2 b1v[4], d1v[4], b0v[4];
#pragma unroll
    for (int blk = 0; blk < 4; blk++) {
        int cg = blk * 64 + colb;
        b1v[blk] = make_float2(ebih1[cg] + ebhh1[cg], ebih1[cg + 1] + ebhh1[cg + 1]);
        d1v[blk] = make_float2(dbih1[cg] + dbhh1[cg], dbih1[cg + 1] + dbhh1[cg + 1]);
        b0v[blk] = make_float2(dbih0[cg] + dbhh0[cg], dbih0[cg + 1] + dbhh0[cg + 1]);
    }
    float fcbr = fcBias[tid & 7];

    // ---- encoder weight fill (bf16 B-frag) ----
    for (int idx = tid; idx < HID * NG; idx += 512) {
        int k = idx >> 8, n = idx & 255;
        w0h[wbidx16(k, n)]      = __float2bfloat16(eWhh0[n * HID + k]);
        w1h[wbidx16(k, n)]      = __float2bfloat16(eWih1[n * HID + k]);
        w1h[wbidx16(k + 64, n)] = __float2bfloat16(eWhh1[n * HID + k]);
    }
    for (int idx = tid; idx < 1024; idx += 512) {
        hF0A[idx] = 0u; hF0B[idx] = 0u; hF1A[idx] = 0u; hF1B[idx] = 0u;
    }
    __syncthreads();

    float c0[4] = {}, c1[4] = {};
    float acc0[4][4], acc1[4][4], hn[4];
    float2 xgv[2][4];

    // ================= encoder: fused L1(i)+L0(i+1), ONE barrier/iter =======
    // Prologue: h0(0) = cell(xg(0)) -> hF0A
    {
#pragma unroll
        for (int rh = 0; rh < 2; rh++) {
            const float* srow = g_xg0 +
                ((size_t)(b0 + mt * 16 + rh * 8 + g) * T_ENC + 0) * NG + colb;
#pragma unroll
            for (int blk = 0; blk < 4; blk++) {
                float2 v = *(const float2*)(srow + blk * 64);
                acc0[blk][rh * 2] = v.x;
                acc0[blk][rh * 2 + 1] = v.y;
            }
        }
        cell_half(acc0, c0, hn);
        hstore_half(hn, hF0A, lane, wq, mt);
        __syncthreads();
    }

    // Iter i computes h1(i) and h0(i+1), i = 0..T_ENC-2
    for (int i = 0; i < T_ENC - 1; i++) {
        u32* h0cur = (i & 1) ? hF0B : hF0A;
        u32* h0nxt = (i & 1) ? hF0A : hF0B;
        u32* h1rd  = (i & 1) ? hF1A : hF1B;    // h1(i-1); h1(-1)=0 in hF1B
        u32* h1wr  = (i & 1) ? hF1B : hF1A;    // h1(i)

#pragma unroll
        for (int blk = 0; blk < 4; blk++) {
            acc1[blk][0] = b1v[blk].x; acc1[blk][1] = b1v[blk].y;
            acc1[blk][2] = b1v[blk].x; acc1[blk][3] = b1v[blk].y;
            acc0[blk][0] = 0.f; acc0[blk][1] = 0.f;
            acc0[blk][2] = 0.f; acc0[blk][3] = 0.f;
        }

        // h0(i) feeds BOTH Wih1 (acc1) and Whh0 (acc0) — shared A loads
        gemm_dual_half(acc1, acc0, h0cur + mtoff, w1u, w0u, lane, wq);

        // prefetch xg(i+1); covered by the h1 GEMM below
#pragma unroll
        for (int rh = 0; rh < 2; rh++) {
            const float* srow = g_xg0 +
                ((size_t)(b0 + mt * 16 + rh * 8 + g) * T_ENC + (i + 1)) * NG + colb;
#pragma unroll
            for (int blk = 0; blk < 4; blk++)
                xgv[rh][blk] = *(const float2*)(srow + blk * 64);
        }

        // acc1 += Whh1 x h1(i-1)
        gemm_half(acc1, h1rd + mtoff, w1u + 8192, 4, lane, wq);

        cell_half(acc1, c1, hn);
        hstore_half(hn, h1wr, lane, wq, mt);   // WAR-safe: alternate buffer

#pragma unroll
        for (int blk = 0; blk < 4; blk++) {
            acc0[blk][0] += xgv[0][blk].x;
            acc0[blk][1] += xgv[0][blk].y;
            acc0[blk][2] += xgv[1][blk].x;
            acc0[blk][3] += xgv[1][blk].y;
        }
        cell_half(acc0, c0, hn);
        hstore_half(hn, h0nxt, lane, wq, mt);  // WAR-safe: alternate buffer

        __syncthreads();                        // publish h1(i), h0(i+1)
    }

    // Epilogue: h1(167). h0(167) in hF0B; h1(166) in hF1A.
    {
#pragma unroll
        for (int blk = 0; blk < 4; blk++) {
            acc1[blk][0] = b1v[blk].x; acc1[blk][1] = b1v[blk].y;
            acc1[blk][2] = b1v[blk].x; acc1[blk][3] = b1v[blk].y;
        }
        gemm_half(acc1, hF0B + mtoff, w1u, 4, lane, wq);
        gemm_half(acc1, hF1A + mtoff, w1u + 8192, 4, lane, wq);
        cell_half(acc1, c1, hn);
        __syncthreads();                        // all reads of hF1A done
        hstore_half(hn, hF1A, lane, wq, mt);   // h1(167) -> A
        for (int idx = tid; idx < 1024; idx += 512) hF0A[idx] = hF0B[idx];
        __syncthreads();
    }

    // ---- decoder weight fill ----
    // Zero w0 kb-block 0 half=1 region (k 8..15 pad for Wih0). Disjoint from
    // the Wih0 fill (which covers all of half=0), so no extra barrier needed.
    for (int idx = tid; idx < 8 * 128; idx += 512) {
        int wqz = idx >> 7, j = idx & 127;
        w0u[(wqz * 2 + 1) * 128 + j] = 0u;
    }
    for (int idx = tid; idx < NT * NG; idx += 512) {      // Wih0: kb 0, k<8
        int k = idx >> 8, n = idx & 255;
        w0h[wbidx16(k, n)] = __float2bfloat16(dWih0[n * NT + k]);
    }
    for (int idx = tid; idx < HID * NG; idx += 512) {
        int k = idx >> 8, n = idx & 255;
        w0h[wbidx16(k + 16, n)] = __float2bfloat16(dWhh0[n * HID + k]);  // kb 1..4
        w1h[wbidx16(k, n)]      = __float2bfloat16(dWih1[n * HID + k]);
        w1h[wbidx16(k + 64, n)] = __float2bfloat16(dWhh1[n * HID + k]);
    }
    for (int idx = tid; idx < 256; idx += 512) dinA[idx] = 0u;
    __syncthreads();

    // ================= decoder =================
    for (int s = 0; s < T_DEC; s++) {
        // L0: b0 + Wih0 x din (kb 0) + Whh0 x h0 (kb 1..4)
#pragma unroll
        for (int blk = 0; blk < 4; blk++) {
            acc0[blk][0] = b0v[blk].x; acc0[blk][1] = b0v[blk].y;
            acc0[blk][2] = b0v[blk].x; acc0[blk][3] = b0v[blk].y;
        }
        gemm_half(acc0, dinA + mtoff, w0u, 1, lane, wq);
        gemm_half(acc0, hF0A + mtoff, w0u + 2048, 4, lane, wq);
        cell_half(acc0, c0, hn);
        __syncthreads();
        hstore_half(hn, hF0A, lane, wq, mt);
        __syncthreads();

        // L1: d1 + Wih1 x h0 + Whh1 x h1
#pragma unroll
        for (int blk = 0; blk < 4; blk++) {
            acc1[blk][0] = d1v[blk].x; acc1[blk][1] = d1v[blk].y;
            acc1[blk][2] = d1v[blk].x; acc1[blk][3] = d1v[blk].y;
        }
        gemm_half(acc1, hF0A + mtoff, w1u, 4, lane, wq);
        gemm_half(acc1, hF1A + mtoff, w1u + 8192, 4, lane, wq);
        cell_half(acc1, c1, hn);
        __syncthreads();
        hstore_half(hn, hF1A, lane, wq, mt);
        // plain fp32 h1 copy for the FC
#pragma unroll
        for (int d = 0; d < 4; d++) {
            int r = mt * 16 + (d >> 1) * 8 + g;
            int j = colb + (d & 1);
            h1plain[j * 32 + r] = hn[d];
        }
        __syncthreads();                 // h1plain visible to FC

        // FC: threads 0..255, one (row, out) each
        if (tid < 256) {
            int r = tid >> 3, o = tid & 7;
            float a = fcbr;
#pragma unroll 8
            for (int j = 0; j < HID; j++)
                a = fmaf(h1plain[j * 32 + r], fcW[o * HID + j], a);
            out[((size_t)(b0 + r) * T_DEC + s) * NT + o] = a;
            // scatter into din bf16 A-frag: kb=0, half=0
            int mtp = r >> 4, rr = r & 15, rh2 = rr >> 3, gr = rr & 7;
            int lane2 = (gr << 2) | (o >> 1);
            int u32idx = (mtp * 32 + lane2) * 4 + rh2;
            ((__nv_bfloat16*)dinA)[u32idx * 2 + (o & 1)] = __float2bfloat16(a);
        }
        __syncthreads();                 // dinA visible to next L0
    }
}

// ---------------------------------------------------------------------------
extern "C" void kernel_launch(void* const* d_in, const int* in_sizes, int n_in,
                              void* d_out, int out_size)
{
    const float* x     = (const float*)d_in[0];
    const float* eWih0 = (const float*)d_in[1];
    const float* eWhh0 = (const float*)d_in[2];
    const float* ebih0 = (const float*)d_in[3];
    const float* ebhh0 = (const float*)d_in[4];
    const float* eWih1 = (const float*)d_in[5];
    const float* eWhh1 = (const float*)d_in[6];
    const float* ebih1 = (const float*)d_in[7];
    const float* ebhh1 = (const float*)d_in[8];
    const float* dWih0 = (const float*)d_in[9];
    const float* dWhh0 = (const float*)d_in[10];
    const float* dbih0 = (const float*)d_in[11];
    const float* dbhh0 = (const float*)d_in[12];
    const float* dWih1 = (const float*)d_in[13];
    const float* dWhh1 = (const float*)d_in[14];
    const float* dbih1 = (const float*)d_in[15];
    const float* dbhh1 = (const float*)d_in[16];
    const float* fcW   = (const float*)d_in[17];
    const float* fcb   = (const float*)d_in[18];
    float* out = (float*)d_out;

    cudaFuncSetAttribute(seq2seq_kernel,
                         cudaFuncAttributeMaxDynamicSharedMemorySize, SMEM_BYTES);

    xg0_kernel<<<B_TOT / 32, 256>>>(x, eWih0, ebih0, ebhh0);
    seq2seq_kernel<<<B_TOT / 32, 512, SMEM_BYTES>>>(
        eWhh0, eWih1, eWhh1, ebih1, ebhh1,
        dWih0, dWhh0, dbih0, dbhh0, dWih1, dWhh1, dbih1, dbhh1,
        fcW, fcb, out);
}